// round 5
// baseline (speedup 1.0000x reference)
#include <cuda_runtime.h>
#include <cstdint>

// Problem constants
#define B_   8
#define L_   1024
#define K_   30
#define EF_  128     // EDGE_FEATURES
#define EIN_ 416     // NUM_PE + NUM_RBF*25
#define NPE_ 16
#define PEC_ 66      // 2*MAX_REL+2
#define NEDGE (B_*L_*K_)     // 245760

// Edge-kernel tiling
#define EB_  64      // edges per block
#define KT_  104     // k-chunk (416 = 4*104)

// ---------------- scratch (static device globals; no allocation) -------------
__device__ float g_X5[B_*L_*15];        // [b,l,5,3]
__device__ int   g_Eidx[NEDGE];
__device__ float g_Wt[EIN_*EF_];        // W_edge transposed: [k][o]

// ---------------- kernel 1: build X5 (Cb atom) + passthrough X ---------------
__global__ void prep_kernel(const float* __restrict__ X, float* __restrict__ outX) {
    int t = blockIdx.x * blockDim.x + threadIdx.x;
    if (t >= B_*L_) return;
    const float* x = X + (size_t)t * 12;
    float x0x=x[0], x0y=x[1],  x0z=x[2];
    float x1x=x[3], x1y=x[4],  x1z=x[5];
    float x2x=x[6], x2y=x[7],  x2z=x[8];
    float bx=x1x-x0x, by=x1y-x0y, bz=x1z-x0z;
    float cx=x2x-x1x, cy=x2y-x1y, cz=x2z-x1z;
    float ax=by*cz-bz*cy, ay=bz*cx-bx*cz, az=bx*cy-by*cx;
    float cbx = -0.58273431f*ax + 0.56802827f*bx - 0.54067466f*cx + x1x;
    float cby = -0.58273431f*ay + 0.56802827f*by - 0.54067466f*cy + x1y;
    float cbz = -0.58273431f*az + 0.56802827f*bz - 0.54067466f*cz + x1z;
    float* o = g_X5 + t*15;
    #pragma unroll
    for (int i = 0; i < 12; i++) { o[i] = x[i]; outX[(size_t)t*12 + i] = x[i]; }
    o[12]=cbx; o[13]=cby; o[14]=cbz;
}

// ---------------- kernel 2: transpose W_edge [128,416] -> [416,128] ----------
__global__ void wt_kernel(const float* __restrict__ W) {
    int idx = blockIdx.x * blockDim.x + threadIdx.x;
    if (idx >= EIN_*EF_) return;
    int k = idx / EF_, o = idx % EF_;
    g_Wt[idx] = W[o*EIN_ + k];
}

// ---------------- kernel 3: per-row distances + stable top-30 ---------------
// One block per (b,i). Matches lax.top_k(-D_adjust): ascending distance,
// ties broken by lower index (packed u64 key).
__global__ __launch_bounds__(256) void topk_kernel(const float* __restrict__ mask,
                                                   float* __restrict__ outEidxF) {
    __shared__ float sD[L_];
    __shared__ unsigned long long sKey[L_];
    __shared__ float sMaxW[8];
    __shared__ unsigned long long sMinW[8];

    int bi = blockIdx.x;           // 0..8191
    int b  = bi >> 10;
    int tid = threadIdx.x, lane = tid & 31, warp = tid >> 5;

    const float* x5b = g_X5 + (size_t)b * L_ * 15;
    int il = bi & (L_-1);
    float cix = x5b[il*15+3], ciy = x5b[il*15+4], ciz = x5b[il*15+5];
    float mi = mask[bi];

    float lmax = -1e30f;
    for (int j = tid; j < L_; j += 256) {
        float dx = cix - x5b[j*15+3];
        float dy = ciy - x5b[j*15+4];
        float dz = ciz - x5b[j*15+5];
        float m2 = mi * mask[b*L_ + j];
        float D  = m2 * sqrtf(dx*dx + dy*dy + dz*dz + 1e-6f);
        sD[j] = D;
        lmax = fmaxf(lmax, D);
    }
    #pragma unroll
    for (int off = 16; off; off >>= 1)
        lmax = fmaxf(lmax, __shfl_xor_sync(0xffffffffu, lmax, off));
    if (lane == 0) sMaxW[warp] = lmax;
    __syncthreads();
    if (tid == 0) {
        float m = sMaxW[0];
        #pragma unroll
        for (int w = 1; w < 8; w++) m = fmaxf(m, sMaxW[w]);
        sMaxW[0] = m;
    }
    __syncthreads();
    float Dmax = sMaxW[0];

    for (int j = tid; j < L_; j += 256) {
        float m2 = mi * mask[b*L_ + j];
        float adj = sD[j] + (1.0f - m2) * Dmax;
        sKey[j] = ((unsigned long long)__float_as_uint(adj) << 32) | (unsigned)j;
    }
    __syncthreads();

    for (int it = 0; it < K_; it++) {
        unsigned long long lm = ~0ull;
        #pragma unroll
        for (int r = 0; r < L_/256; r++) {
            unsigned long long v = sKey[tid + r*256];
            lm = (v < lm) ? v : lm;
        }
        #pragma unroll
        for (int off = 16; off; off >>= 1) {
            unsigned long long v = __shfl_xor_sync(0xffffffffu, lm, off);
            lm = (v < lm) ? v : lm;
        }
        if (lane == 0) sMinW[warp] = lm;
        __syncthreads();
        if (tid == 0) {
            unsigned long long m = sMinW[0];
            #pragma unroll
            for (int w = 1; w < 8; w++) { unsigned long long v = sMinW[w]; m = (v < m) ? v : m; }
            int idx = (int)(m & 0xffffffffu);
            g_Eidx[bi*K_ + it]   = idx;
            outEidxF[bi*K_ + it] = (float)idx;
            sKey[idx] = ~0ull;
        }
        __syncthreads();
    }
}

// ---------------- kernel 4: edge features + 416->128 matvec + LayerNorm -----
// 64 edges/block, 256 threads (8 warps). Warp w owns edges [w*8, w*8+8),
// lane l owns output channels 4l..4l+3. W chunk staged k-major in smem
// (conflict-free LDS.128); features read by broadcast LDS.
__global__ __launch_bounds__(256, 1) void edge_kernel(
    const int*   __restrict__ ridx,
    const int*   __restrict__ clab,
    const float* __restrict__ W_pe,
    const float* __restrict__ b_pe,
    const float* __restrict__ ln_w,
    const float* __restrict__ ln_b,
    float*       __restrict__ outE)
{
    extern __shared__ float sm[];
    float* f_s    = sm;                       // EB_*EIN_ = 26624
    float* Wc     = f_s    + EB_*EIN_;        // KT_*EF_  = 13312
    float* dist_s = Wc     + KT_*EF_;         // EB_*25   = 1600
    float* Wpe_s  = dist_s + EB_*25;          // 1056
    float* bpe_s  = Wpe_s  + NPE_*PEC_;       // 16
    float* lnw_s  = bpe_s  + NPE_;            // 128
    float* lnb_s  = lnw_s  + EF_;             // 128
    int*   sI     = (int*)(lnb_s + EF_);      // EB_
    int*   sN     = sI + EB_;                 // EB_
    int*   sd     = sN + EB_;                 // EB_

    int tid = threadIdx.x, lane = tid & 31, warp = tid >> 5;
    int blk = blockIdx.x;

    // small caches
    for (int i = tid; i < NPE_*PEC_; i += 256) Wpe_s[i] = W_pe[i];
    if (tid < NPE_) bpe_s[tid] = b_pe[tid];
    if (tid < EF_)  { lnw_s[tid] = ln_w[tid]; lnb_s[tid] = ln_b[tid]; }

    // edge metadata + positional-encoding class
    if (tid < EB_) {
        int eg  = blk*EB_ + tid;
        int b   = eg / (L_*K_);
        int r   = eg % (L_*K_);
        int i   = r / K_;
        int nbr = g_Eidx[eg];
        int gi = b*L_ + i, gn = b*L_ + nbr;
        sI[tid] = gi; sN[tid] = gn;
        int off  = ridx[gi] - ridx[gn];
        int same = (clab[gi] == clab[gn]);
        int c = off + 32; c = c < 0 ? 0 : (c > 64 ? 64 : c);
        sd[tid] = same ? c : 65;
    }
    __syncthreads();

    // 25 inter-atom distances per edge
    for (int w = tid; w < EB_*25; w += 256) {
        int e = w / 25, p = w % 25;
        int a = p / 5, bb = p % 5;
        const float* xi = g_X5 + sI[e]*15 + a*3;
        const float* xn = g_X5 + sN[e]*15 + bb*3;
        float dx = xi[0]-xn[0], dy = xi[1]-xn[1], dz = xi[2]-xn[2];
        dist_s[w] = sqrtf(dx*dx + dy*dy + dz*dz + 1e-6f);
    }
    // positional-encoding features (first 16)
    for (int w = tid; w < EB_*NPE_; w += 256) {
        int e = w >> 4, p = w & 15;
        f_s[e*EIN_ + p] = Wpe_s[p*PEC_ + sd[e]] + bpe_s[p];
    }
    __syncthreads();

    // RBF features (400 per edge)
    for (int w = tid; w < EB_*400; w += 256) {
        int e = w / 400, q = w % 400;
        int pr = q >> 4, m = q & 15;
        float d  = dist_s[e*25 + pr];
        float mu = 2.0f + 1.33333337f * (float)m;   // linspace(2,22,16) step
        float t  = (d - mu) * 0.8f;                  // /1.25
        f_s[e*EIN_ + 16 + q] = __expf(-t*t);
    }

    // ---------------- GEMM: acc[e][4] = f(416) . Wt(416x128) ----------------
    float acc[8][4];
    #pragma unroll
    for (int e = 0; e < 8; e++) { acc[e][0]=0.f; acc[e][1]=0.f; acc[e][2]=0.f; acc[e][3]=0.f; }

    const float* fw = f_s + (warp*8)*EIN_;

    #pragma unroll 1
    for (int kc = 0; kc < EIN_; kc += KT_) {
        __syncthreads();   // previous chunk consumed (and 1st iter: f_s ready)
        {
            const float4* src = (const float4*)(g_Wt + (size_t)kc*EF_);
            float4* dst = (float4*)Wc;
            #pragma unroll
            for (int i = 0; i < (KT_*EF_/4)/256; i++) dst[tid + i*256] = src[tid + i*256];
        }
        __syncthreads();

        #pragma unroll 4
        for (int kk = 0; kk < KT_; kk++) {
            float4 w4 = *(const float4*)(Wc + kk*EF_ + lane*4);
            const float* fp = fw + kc + kk;
            #pragma unroll
            for (int e = 0; e < 8; e++) {
                float f = fp[e*EIN_];          // broadcast LDS
                acc[e][0] += w4.x * f;
                acc[e][1] += w4.y * f;
                acc[e][2] += w4.z * f;
                acc[e][3] += w4.w * f;
            }
        }
    }

    // ---------------- LayerNorm over 128 channels + store -------------------
    const float inv128 = 1.0f / 128.0f;
    float lw0 = lnw_s[lane*4+0], lw1 = lnw_s[lane*4+1], lw2 = lnw_s[lane*4+2], lw3 = lnw_s[lane*4+3];
    float lb0 = lnb_s[lane*4+0], lb1 = lnb_s[lane*4+1], lb2 = lnb_s[lane*4+2], lb3 = lnb_s[lane*4+3];

    #pragma unroll
    for (int e = 0; e < 8; e++) {
        float s = acc[e][0] + acc[e][1] + acc[e][2] + acc[e][3];
        #pragma unroll
        for (int off = 16; off; off >>= 1) s += __shfl_xor_sync(0xffffffffu, s, off);
        float mean = s * inv128;
        float d0 = acc[e][0]-mean, d1 = acc[e][1]-mean, d2 = acc[e][2]-mean, d3 = acc[e][3]-mean;
        float v = d0*d0 + d1*d1 + d2*d2 + d3*d3;
        #pragma unroll
        for (int off = 16; off; off >>= 1) v += __shfl_xor_sync(0xffffffffu, v, off);
        float rstd = rsqrtf(v * inv128 + 1e-5f);
        float4 o;
        o.x = d0*rstd*lw0 + lb0;
        o.y = d1*rstd*lw1 + lb1;
        o.z = d2*rstd*lw2 + lb2;
        o.w = d3*rstd*lw3 + lb3;
        size_t eg = (size_t)blk*EB_ + warp*8 + e;
        *(float4*)(outE + eg*EF_ + lane*4) = o;
    }
}

// ---------------------------------------------------------------------------
extern "C" void kernel_launch(void* const* d_in, const int* in_sizes, int n_in,
                              void* d_out, int out_size) {
    (void)in_sizes; (void)n_in; (void)out_size;
    const float* X      = (const float*)d_in[0];
    const float* mask   = (const float*)d_in[1];
    const int*   ridx   = (const int*)  d_in[2];
    const int*   clab   = (const int*)  d_in[3];
    const float* W_pe   = (const float*)d_in[4];
    const float* b_pe   = (const float*)d_in[5];
    const float* W_edge = (const float*)d_in[6];
    const float* ln_w   = (const float*)d_in[7];
    const float* ln_b   = (const float*)d_in[8];

    float* out      = (float*)d_out;
    float* outE     = out;                                   // B*L*K*128
    float* outEidxF = out + (size_t)NEDGE * EF_;             // B*L*K (as float)
    float* outX     = outEidxF + (size_t)NEDGE;              // B*L*4*3

    const int smem_bytes = (EB_*EIN_ + KT_*EF_ + EB_*25 + NPE_*PEC_ + NPE_ + 2*EF_) * 4
                         + EB_ * 3 * 4;   // = 172224
    cudaFuncSetAttribute(edge_kernel, cudaFuncAttributeMaxDynamicSharedMemorySize, smem_bytes);

    prep_kernel<<<(B_*L_ + 255)/256, 256>>>(X, outX);
    wt_kernel  <<<(EIN_*EF_ + 255)/256, 256>>>(W_edge);
    topk_kernel<<<B_*L_, 256>>>(mask, outEidxF);
    edge_kernel<<<NEDGE/EB_, 256, smem_bytes>>>(ridx, clab, W_pe, b_pe, ln_w, ln_b, outE);
}

// round 6
// speedup vs baseline: 1.0001x; 1.0001x over previous
#include <cuda_runtime.h>
#include <cstdint>

// Problem constants
#define B_   8
#define L_   1024
#define K_   30
#define EF_  128     // EDGE_FEATURES
#define EIN_ 416     // NUM_PE + NUM_RBF*25
#define NPE_ 16
#define PEC_ 66      // 2*MAX_REL+2
#define NEDGE (B_*L_*K_)     // 245760

// Edge-kernel tiling
#define EB_  64      // edges per block
#define KT_  104     // k-chunk (416 = 4*104)

// ---------------- scratch (static device globals; no allocation) -------------
__device__ float g_X5[B_*L_*15];        // [b,l,5,3]
__device__ int   g_Eidx[NEDGE];
__device__ float g_Wt[EIN_*EF_];        // W_edge transposed: [k][o]

// ---------------- kernel 1: build X5 (Cb atom) + passthrough X ---------------
__global__ void prep_kernel(const float* __restrict__ X, float* __restrict__ outX) {
    int t = blockIdx.x * blockDim.x + threadIdx.x;
    if (t >= B_*L_) return;
    const float* x = X + (size_t)t * 12;
    float x0x=x[0], x0y=x[1],  x0z=x[2];
    float x1x=x[3], x1y=x[4],  x1z=x[5];
    float x2x=x[6], x2y=x[7],  x2z=x[8];
    float bx=x1x-x0x, by=x1y-x0y, bz=x1z-x0z;
    float cx=x2x-x1x, cy=x2y-x1y, cz=x2z-x1z;
    float ax=by*cz-bz*cy, ay=bz*cx-bx*cz, az=bx*cy-by*cx;
    float cbx = -0.58273431f*ax + 0.56802827f*bx - 0.54067466f*cx + x1x;
    float cby = -0.58273431f*ay + 0.56802827f*by - 0.54067466f*cy + x1y;
    float cbz = -0.58273431f*az + 0.56802827f*bz - 0.54067466f*cz + x1z;
    float* o = g_X5 + t*15;
    #pragma unroll
    for (int i = 0; i < 12; i++) { o[i] = x[i]; outX[(size_t)t*12 + i] = x[i]; }
    o[12]=cbx; o[13]=cby; o[14]=cbz;
}

// ---------------- kernel 2: transpose W_edge [128,416] -> [416,128] ----------
__global__ void wt_kernel(const float* __restrict__ W) {
    int idx = blockIdx.x * blockDim.x + threadIdx.x;
    if (idx >= EIN_*EF_) return;
    int k = idx / EF_, o = idx % EF_;
    g_Wt[idx] = W[o*EIN_ + k];
}

// ---------------- kernel 3: per-row distances + stable top-30 ---------------
// One block per (b,i). Matches lax.top_k(-D_adjust): ascending distance,
// ties broken by lower index (packed u64 key).
__global__ __launch_bounds__(256) void topk_kernel(const float* __restrict__ mask,
                                                   float* __restrict__ outEidxF) {
    __shared__ float sD[L_];
    __shared__ unsigned long long sKey[L_];
    __shared__ float sMaxW[8];
    __shared__ unsigned long long sMinW[8];

    int bi = blockIdx.x;           // 0..8191
    int b  = bi >> 10;
    int tid = threadIdx.x, lane = tid & 31, warp = tid >> 5;

    const float* x5b = g_X5 + (size_t)b * L_ * 15;
    int il = bi & (L_-1);
    float cix = x5b[il*15+3], ciy = x5b[il*15+4], ciz = x5b[il*15+5];
    float mi = mask[bi];

    float lmax = -1e30f;
    for (int j = tid; j < L_; j += 256) {
        float dx = cix - x5b[j*15+3];
        float dy = ciy - x5b[j*15+4];
        float dz = ciz - x5b[j*15+5];
        float m2 = mi * mask[b*L_ + j];
        float D  = m2 * sqrtf(dx*dx + dy*dy + dz*dz + 1e-6f);
        sD[j] = D;
        lmax = fmaxf(lmax, D);
    }
    #pragma unroll
    for (int off = 16; off; off >>= 1)
        lmax = fmaxf(lmax, __shfl_xor_sync(0xffffffffu, lmax, off));
    if (lane == 0) sMaxW[warp] = lmax;
    __syncthreads();
    if (tid == 0) {
        float m = sMaxW[0];
        #pragma unroll
        for (int w = 1; w < 8; w++) m = fmaxf(m, sMaxW[w]);
        sMaxW[0] = m;
    }
    __syncthreads();
    float Dmax = sMaxW[0];

    for (int j = tid; j < L_; j += 256) {
        float m2 = mi * mask[b*L_ + j];
        float adj = sD[j] + (1.0f - m2) * Dmax;
        sKey[j] = ((unsigned long long)__float_as_uint(adj) << 32) | (unsigned)j;
    }
    __syncthreads();

    for (int it = 0; it < K_; it++) {
        unsigned long long lm = ~0ull;
        #pragma unroll
        for (int r = 0; r < L_/256; r++) {
            unsigned long long v = sKey[tid + r*256];
            lm = (v < lm) ? v : lm;
        }
        #pragma unroll
        for (int off = 16; off; off >>= 1) {
            unsigned long long v = __shfl_xor_sync(0xffffffffu, lm, off);
            lm = (v < lm) ? v : lm;
        }
        if (lane == 0) sMinW[warp] = lm;
        __syncthreads();
        if (tid == 0) {
            unsigned long long m = sMinW[0];
            #pragma unroll
            for (int w = 1; w < 8; w++) { unsigned long long v = sMinW[w]; m = (v < m) ? v : m; }
            int idx = (int)(m & 0xffffffffu);
            g_Eidx[bi*K_ + it]   = idx;
            outEidxF[bi*K_ + it] = (float)idx;
            sKey[idx] = ~0ull;
        }
        __syncthreads();
    }
}

// ---------------- kernel 4: edge features + 416->128 matvec + LayerNorm -----
// 64 edges/block, 256 threads (8 warps). Warp w owns edges [w*8, w*8+8),
// lane l owns output channels 4l..4l+3. W chunk staged k-major in smem
// (conflict-free LDS.128); features read by broadcast LDS.
__global__ __launch_bounds__(256, 1) void edge_kernel(
    const int*   __restrict__ ridx,
    const int*   __restrict__ clab,
    const float* __restrict__ W_pe,
    const float* __restrict__ b_pe,
    const float* __restrict__ ln_w,
    const float* __restrict__ ln_b,
    float*       __restrict__ outE)
{
    extern __shared__ float sm[];
    float* f_s    = sm;                       // EB_*EIN_ = 26624
    float* Wc     = f_s    + EB_*EIN_;        // KT_*EF_  = 13312
    float* dist_s = Wc     + KT_*EF_;         // EB_*25   = 1600
    float* Wpe_s  = dist_s + EB_*25;          // 1056
    float* bpe_s  = Wpe_s  + NPE_*PEC_;       // 16
    float* lnw_s  = bpe_s  + NPE_;            // 128
    float* lnb_s  = lnw_s  + EF_;             // 128
    int*   sI     = (int*)(lnb_s + EF_);      // EB_
    int*   sN     = sI + EB_;                 // EB_
    int*   sd     = sN + EB_;                 // EB_

    int tid = threadIdx.x, lane = tid & 31, warp = tid >> 5;
    int blk = blockIdx.x;

    // small caches
    for (int i = tid; i < NPE_*PEC_; i += 256) Wpe_s[i] = W_pe[i];
    if (tid < NPE_) bpe_s[tid] = b_pe[tid];
    if (tid < EF_)  { lnw_s[tid] = ln_w[tid]; lnb_s[tid] = ln_b[tid]; }

    // edge metadata + positional-encoding class
    if (tid < EB_) {
        int eg  = blk*EB_ + tid;
        int b   = eg / (L_*K_);
        int r   = eg % (L_*K_);
        int i   = r / K_;
        int nbr = g_Eidx[eg];
        int gi = b*L_ + i, gn = b*L_ + nbr;
        sI[tid] = gi; sN[tid] = gn;
        int off  = ridx[gi] - ridx[gn];
        int same = (clab[gi] == clab[gn]);
        int c = off + 32; c = c < 0 ? 0 : (c > 64 ? 64 : c);
        sd[tid] = same ? c : 65;
    }
    __syncthreads();

    // 25 inter-atom distances per edge
    for (int w = tid; w < EB_*25; w += 256) {
        int e = w / 25, p = w % 25;
        int a = p / 5, bb = p % 5;
        const float* xi = g_X5 + sI[e]*15 + a*3;
        const float* xn = g_X5 + sN[e]*15 + bb*3;
        float dx = xi[0]-xn[0], dy = xi[1]-xn[1], dz = xi[2]-xn[2];
        dist_s[w] = sqrtf(dx*dx + dy*dy + dz*dz + 1e-6f);
    }
    // positional-encoding features (first 16)
    for (int w = tid; w < EB_*NPE_; w += 256) {
        int e = w >> 4, p = w & 15;
        f_s[e*EIN_ + p] = Wpe_s[p*PEC_ + sd[e]] + bpe_s[p];
    }
    __syncthreads();

    // RBF features (400 per edge)
    for (int w = tid; w < EB_*400; w += 256) {
        int e = w / 400, q = w % 400;
        int pr = q >> 4, m = q & 15;
        float d  = dist_s[e*25 + pr];
        float mu = 2.0f + 1.33333337f * (float)m;   // linspace(2,22,16) step
        float t  = (d - mu) * 0.8f;                  // /1.25
        f_s[e*EIN_ + 16 + q] = __expf(-t*t);
    }

    // ---------------- GEMM: acc[e][4] = f(416) . Wt(416x128) ----------------
    float acc[8][4];
    #pragma unroll
    for (int e = 0; e < 8; e++) { acc[e][0]=0.f; acc[e][1]=0.f; acc[e][2]=0.f; acc[e][3]=0.f; }

    const float* fw = f_s + (warp*8)*EIN_;

    #pragma unroll 1
    for (int kc = 0; kc < EIN_; kc += KT_) {
        __syncthreads();   // previous chunk consumed (and 1st iter: f_s ready)
        {
            const float4* src = (const float4*)(g_Wt + (size_t)kc*EF_);
            float4* dst = (float4*)Wc;
            #pragma unroll
            for (int i = 0; i < (KT_*EF_/4)/256; i++) dst[tid + i*256] = src[tid + i*256];
        }
        __syncthreads();

        #pragma unroll 4
        for (int kk = 0; kk < KT_; kk++) {
            float4 w4 = *(const float4*)(Wc + kk*EF_ + lane*4);
            const float* fp = fw + kc + kk;
            #pragma unroll
            for (int e = 0; e < 8; e++) {
                float f = fp[e*EIN_];          // broadcast LDS
                acc[e][0] += w4.x * f;
                acc[e][1] += w4.y * f;
                acc[e][2] += w4.z * f;
                acc[e][3] += w4.w * f;
            }
        }
    }

    // ---------------- LayerNorm over 128 channels + store -------------------
    const float inv128 = 1.0f / 128.0f;
    float lw0 = lnw_s[lane*4+0], lw1 = lnw_s[lane*4+1], lw2 = lnw_s[lane*4+2], lw3 = lnw_s[lane*4+3];
    float lb0 = lnb_s[lane*4+0], lb1 = lnb_s[lane*4+1], lb2 = lnb_s[lane*4+2], lb3 = lnb_s[lane*4+3];

    #pragma unroll
    for (int e = 0; e < 8; e++) {
        float s = acc[e][0] + acc[e][1] + acc[e][2] + acc[e][3];
        #pragma unroll
        for (int off = 16; off; off >>= 1) s += __shfl_xor_sync(0xffffffffu, s, off);
        float mean = s * inv128;
        float d0 = acc[e][0]-mean, d1 = acc[e][1]-mean, d2 = acc[e][2]-mean, d3 = acc[e][3]-mean;
        float v = d0*d0 + d1*d1 + d2*d2 + d3*d3;
        #pragma unroll
        for (int off = 16; off; off >>= 1) v += __shfl_xor_sync(0xffffffffu, v, off);
        float rstd = rsqrtf(v * inv128 + 1e-5f);
        float4 o;
        o.x = d0*rstd*lw0 + lb0;
        o.y = d1*rstd*lw1 + lb1;
        o.z = d2*rstd*lw2 + lb2;
        o.w = d3*rstd*lw3 + lb3;
        size_t eg = (size_t)blk*EB_ + warp*8 + e;
        *(float4*)(outE + eg*EF_ + lane*4) = o;
    }
}

// ---------------------------------------------------------------------------
extern "C" void kernel_launch(void* const* d_in, const int* in_sizes, int n_in,
                              void* d_out, int out_size) {
    (void)in_sizes; (void)n_in; (void)out_size;
    const float* X      = (const float*)d_in[0];
    const float* mask   = (const float*)d_in[1];
    const int*   ridx   = (const int*)  d_in[2];
    const int*   clab   = (const int*)  d_in[3];
    const float* W_pe   = (const float*)d_in[4];
    const float* b_pe   = (const float*)d_in[5];
    const float* W_edge = (const float*)d_in[6];
    const float* ln_w   = (const float*)d_in[7];
    const float* ln_b   = (const float*)d_in[8];

    float* out      = (float*)d_out;
    float* outE     = out;                                   // B*L*K*128
    float* outEidxF = out + (size_t)NEDGE * EF_;             // B*L*K (as float)
    float* outX     = outEidxF + (size_t)NEDGE;              // B*L*4*3

    const int smem_bytes = (EB_*EIN_ + KT_*EF_ + EB_*25 + NPE_*PEC_ + NPE_ + 2*EF_) * 4
                         + EB_ * 3 * 4;   // = 172224
    cudaFuncSetAttribute(edge_kernel, cudaFuncAttributeMaxDynamicSharedMemorySize, smem_bytes);

    prep_kernel<<<(B_*L_ + 255)/256, 256>>>(X, outX);
    wt_kernel  <<<(EIN_*EF_ + 255)/256, 256>>>(W_edge);
    topk_kernel<<<B_*L_, 256>>>(mask, outEidxF);
    edge_kernel<<<NEDGE/EB_, 256, smem_bytes>>>(ridx, clab, W_pe, b_pe, ln_w, ln_b, outE);
}

// round 9
// speedup vs baseline: 1.4700x; 1.4699x over previous
#include <cuda_runtime.h>
#include <cuda_bf16.h>
#include <cstdint>

// ---------------- problem constants ----------------
#define B_    8
#define L_    1024
#define K_    30
#define EF_   128          // EDGE_FEATURES (= N)
#define EIN_  416          // NUM_PE + NUM_RBF*25 (= K)
#define KPAD_ 448          // K padded to 7*64
#define NPE_  16
#define PEC_  66           // 2*MAX_REL+2
#define NEDGE (B_*L_*K_)   // 245760

// ---------------- edge-kernel tiling ----------------
#define EB_   128          // edges per block (= M)
#define KC_   64           // k per chunk
#define NCH_  7            // KPAD_/KC_
#define SA_   72           // smem row stride in bf16 (64 data + 8 pad; 9*16B -> LDSM conflict-free)

// ---------------- scratch (static device globals) ----------------
__device__ float          g_X5[B_*L_*15];
__device__ int            g_Eidx[NEDGE];
__device__ __nv_bfloat16  g_Whi[EF_*KPAD_];   // W_edge hi part, [n][k] k-major, zero-padded
__device__ __nv_bfloat16  g_Wlo[EF_*KPAD_];   // residual part

// ================= helpers =================
__device__ __forceinline__ uint32_t smem_u32(const void* p) {
    uint32_t a;
    asm("{ .reg .u64 t; cvta.to.shared.u64 t, %1; cvt.u32.u64 %0, t; }" : "=r"(a) : "l"(p));
    return a;
}
__device__ __forceinline__ void sts128(uint32_t addr, uint32_t a, uint32_t b, uint32_t c, uint32_t d) {
    asm volatile("st.shared.v4.b32 [%0], {%1,%2,%3,%4};" :: "r"(addr), "r"(a), "r"(b), "r"(c), "r"(d) : "memory");
}
__device__ __forceinline__ void ldsm4(uint32_t* r, uint32_t addr) {
    asm volatile("ldmatrix.sync.aligned.m8n8.x4.shared.b16 {%0,%1,%2,%3}, [%4];"
        : "=r"(r[0]), "=r"(r[1]), "=r"(r[2]), "=r"(r[3]) : "r"(addr));
}
__device__ __forceinline__ void mma16816(float (&d)[4], const uint32_t* a, const uint32_t* b) {
    asm volatile("mma.sync.aligned.m16n8k16.row.col.f32.bf16.bf16.f32 "
        "{%0,%1,%2,%3}, {%4,%5,%6,%7}, {%8,%9}, {%0,%1,%2,%3};"
        : "+f"(d[0]), "+f"(d[1]), "+f"(d[2]), "+f"(d[3])
        : "r"(a[0]), "r"(a[1]), "r"(a[2]), "r"(a[3]), "r"(b[0]), "r"(b[1]));
}
__device__ __forceinline__ uint32_t pk(__nv_bfloat16 a, __nv_bfloat16 b) {
    return (uint32_t)__bfloat16_as_ushort(a) | ((uint32_t)__bfloat16_as_ushort(b) << 16);
}

// ================= kernel 1: build X5 + passthrough X =================
__global__ void prep_kernel(const float* __restrict__ X, float* __restrict__ outX) {
    int t = blockIdx.x * blockDim.x + threadIdx.x;
    if (t >= B_*L_) return;
    const float* x = X + (size_t)t * 12;
    float x0x=x[0], x0y=x[1],  x0z=x[2];
    float x1x=x[3], x1y=x[4],  x1z=x[5];
    float x2x=x[6], x2y=x[7],  x2z=x[8];
    float bx=x1x-x0x, by=x1y-x0y, bz=x1z-x0z;
    float cx=x2x-x1x, cy=x2y-x1y, cz=x2z-x1z;
    float ax=by*cz-bz*cy, ay=bz*cx-bx*cz, az=bx*cy-by*cx;
    float* o = g_X5 + t*15;
    #pragma unroll
    for (int i = 0; i < 12; i++) { o[i] = x[i]; outX[(size_t)t*12 + i] = x[i]; }
    o[12] = -0.58273431f*ax + 0.56802827f*bx - 0.54067466f*cx + x1x;
    o[13] = -0.58273431f*ay + 0.56802827f*by - 0.54067466f*cy + x1y;
    o[14] = -0.58273431f*az + 0.56802827f*bz - 0.54067466f*cz + x1z;
}

// ================= kernel 2: split W_edge into bf16 hi/lo, padded =================
__global__ void wt_kernel(const float* __restrict__ W) {
    int idx = blockIdx.x * blockDim.x + threadIdx.x;
    if (idx >= EF_*KPAD_) return;
    int n = idx / KPAD_, k = idx % KPAD_;
    float w = (k < EIN_) ? W[n*EIN_ + k] : 0.0f;
    __nv_bfloat16 hi = __float2bfloat16(w);
    float lo = w - __bfloat162float(hi);
    g_Whi[idx] = hi;
    g_Wlo[idx] = __float2bfloat16(lo);
}

// ================= kernel 3: per-row distances + stable top-30 =================
__global__ __launch_bounds__(256) void topk_kernel(const float* __restrict__ mask,
                                                   float* __restrict__ outEidxF) {
    __shared__ float sD[L_];
    __shared__ unsigned long long sKey[L_];
    __shared__ float sMaxW[8];
    __shared__ unsigned long long sMinW[8];

    int bi = blockIdx.x;
    int b  = bi >> 10;
    int tid = threadIdx.x, lane = tid & 31, warp = tid >> 5;

    const float* x5b = g_X5 + (size_t)b * L_ * 15;
    int il = bi & (L_-1);
    float cix = x5b[il*15+3], ciy = x5b[il*15+4], ciz = x5b[il*15+5];
    float mi = mask[bi];

    float lmax = -1e30f;
    for (int j = tid; j < L_; j += 256) {
        float dx = cix - x5b[j*15+3];
        float dy = ciy - x5b[j*15+4];
        float dz = ciz - x5b[j*15+5];
        float m2 = mi * mask[b*L_ + j];
        float D  = m2 * sqrtf(dx*dx + dy*dy + dz*dz + 1e-6f);
        sD[j] = D;
        lmax = fmaxf(lmax, D);
    }
    #pragma unroll
    for (int off = 16; off; off >>= 1)
        lmax = fmaxf(lmax, __shfl_xor_sync(0xffffffffu, lmax, off));
    if (lane == 0) sMaxW[warp] = lmax;
    __syncthreads();
    if (tid == 0) {
        float m = sMaxW[0];
        #pragma unroll
        for (int w = 1; w < 8; w++) m = fmaxf(m, sMaxW[w]);
        sMaxW[0] = m;
    }
    __syncthreads();
    float Dmax = sMaxW[0];

    for (int j = tid; j < L_; j += 256) {
        float m2 = mi * mask[b*L_ + j];
        float adj = sD[j] + (1.0f - m2) * Dmax;
        sKey[j] = ((unsigned long long)__float_as_uint(adj) << 32) | (unsigned)j;
    }
    __syncthreads();

    for (int it = 0; it < K_; it++) {
        unsigned long long lm = ~0ull;
        #pragma unroll
        for (int r = 0; r < L_/256; r++) {
            unsigned long long v = sKey[tid + r*256];
            lm = (v < lm) ? v : lm;
        }
        #pragma unroll
        for (int off = 16; off; off >>= 1) {
            unsigned long long v = __shfl_xor_sync(0xffffffffu, lm, off);
            lm = (v < lm) ? v : lm;
        }
        if (lane == 0) sMinW[warp] = lm;
        __syncthreads();
        if (tid == 0) {
            unsigned long long m = sMinW[0];
            #pragma unroll
            for (int w = 1; w < 8; w++) { unsigned long long v = sMinW[w]; m = (v < m) ? v : m; }
            int idx = (int)(m & 0xffffffffu);
            g_Eidx[bi*K_ + it]   = idx;
            outEidxF[bi*K_ + it] = (float)idx;
            sKey[idx] = ~0ull;
        }
        __syncthreads();
    }
}

// ================= kernel 4: HMMA edge kernel =================
// 128 edges/block, 256 threads. K chunked at 64 (7 chunks). A = features
// (bf16 hi/lo, built on the fly), B = W_edge hi/lo (register-prefetched from
// L2 across the feature build). 8 warps in 4x2 grid, warp tile m32 x n64,
// mma.sync m16n8k16 bf16 with fp32 acc, 3-pass split. Epilogue: in-register
// LayerNorm with quad shuffles + smem cross-warp combine, staged store.

// smem offsets (bytes)
#define SM_RED   0        // 128*2*2 floats = 2048
#define SM_SD    2048     // 512
#define SM_SI    2560     // 512
#define SM_SN    3072     // 512
#define SM_WPE   3584     // 4224
#define SM_BPE   7808     // 64
#define SM_LNW   7872     // 512
#define SM_LNB   8384     // 512
#define SM_DIST  8896     // 12800 -> 21696
#define SM_AH    21760    // 128*SA_*2 = 18432
#define SM_AL    (SM_AH + 18432)
#define SM_BH    (SM_AL + 18432)
#define SM_BL    (SM_BH + 18432)
#define SM_STAGE SM_AH    // 128*132*4 = 67584 (reuses tiles post-GEMM)
#define SMEM_BYTES (SM_BL + 18432)   // 95488

__device__ __forceinline__ float featval(int k, int sde,
                                         const float* __restrict__ Wpe_s,
                                         const float* __restrict__ bpe_s,
                                         const float* __restrict__ dist_e) {
    if (k < NPE_) return Wpe_s[k*PEC_ + sde] + bpe_s[k];
    if (k < EIN_) {
        int q = k - NPE_;
        float d = dist_e[q >> 4];
        int m = q & 15;
        float t = (d - (2.0f + 1.33333337f*(float)m)) * 0.8f;
        return __expf(-t*t);
    }
    return 0.0f;
}

__global__ __launch_bounds__(256, 1) void edge_kernel(
    const int*   __restrict__ ridx,
    const int*   __restrict__ clab,
    const float* __restrict__ W_pe,
    const float* __restrict__ b_pe,
    const float* __restrict__ ln_w,
    const float* __restrict__ ln_b,
    float*       __restrict__ outE)
{
    extern __shared__ char smem[];
    uint32_t sb = smem_u32(smem);
    int tid = threadIdx.x, lane = tid & 31, wid = tid >> 5;
    int blk = blockIdx.x;

    float* red    = (float*)(smem + SM_RED);
    int*   sd     = (int*)  (smem + SM_SD);
    int*   sI     = (int*)  (smem + SM_SI);
    int*   sN     = (int*)  (smem + SM_SN);
    float* Wpe_s  = (float*)(smem + SM_WPE);
    float* bpe_s  = (float*)(smem + SM_BPE);
    float* lnw_s  = (float*)(smem + SM_LNW);
    float* lnb_s  = (float*)(smem + SM_LNB);
    float* dist_s = (float*)(smem + SM_DIST);

    // small caches
    for (int i = tid; i < NPE_*PEC_; i += 256) Wpe_s[i] = W_pe[i];
    if (tid < NPE_) bpe_s[tid] = b_pe[tid];
    if (tid < EF_)  { lnw_s[tid] = ln_w[tid]; lnb_s[tid] = ln_b[tid]; }

    // edge metadata + positional-encoding class
    if (tid < EB_) {
        int eg  = blk*EB_ + tid;
        int b   = eg / (L_*K_);
        int r   = eg % (L_*K_);
        int i   = r / K_;
        int nbr = g_Eidx[eg];
        int gi = b*L_ + i, gn = b*L_ + nbr;
        sI[tid] = gi; sN[tid] = gn;
        int off  = ridx[gi] - ridx[gn];
        int same = (clab[gi] == clab[gn]);
        int c = off + 32; c = c < 0 ? 0 : (c > 64 ? 64 : c);
        sd[tid] = same ? c : 65;
    }
    __syncthreads();

    // 25 inter-atom distances per edge
    for (int w = tid; w < EB_*25; w += 256) {
        int e = w / 25, p = w % 25;
        int a = p / 5, bb = p % 5;
        const float* xi = g_X5 + sI[e]*15 + a*3;
        const float* xn = g_X5 + sN[e]*15 + bb*3;
        float dx = xi[0]-xn[0], dy = xi[1]-xn[1], dz = xi[2]-xn[2];
        dist_s[w] = sqrtf(dx*dx + dy*dy + dz*dz + 1e-6f);
    }
    __syncthreads();

    // lane-invariant ldmatrix address components
    int mw = wid >> 1, nw = wid & 1;
    int arow_l = ((lane>>3)&1)*8 + (lane&7);
    int acoff  = (lane>>4)*8;
    int nrow_l = (lane>>4)*8 + (lane&7);
    int bkoff  = ((lane>>3)&1)*8;
    uint32_t aAh = sb + SM_AH + (uint32_t)((mw*32 + arow_l)*SA_ + acoff)*2;
    uint32_t aAl = sb + SM_AL + (uint32_t)((mw*32 + arow_l)*SA_ + acoff)*2;
    uint32_t aBh = sb + SM_BH + (uint32_t)((nw*64 + nrow_l)*SA_ + bkoff)*2;
    uint32_t aBl = sb + SM_BL + (uint32_t)((nw*64 + nrow_l)*SA_ + bkoff)*2;

    float acc[2][8][4];
    #pragma unroll
    for (int mt = 0; mt < 2; mt++)
        #pragma unroll
        for (int nt = 0; nt < 8; nt++)
            #pragma unroll
            for (int i = 0; i < 4; i++) acc[mt][nt][i] = 0.0f;

    // B-chunk prefetch registers (chunk 0)
    int brow = tid >> 1, bpart = tid & 1;
    uint4 pbh[4], pbl[4];
    {
        const __nv_bfloat16* ph = g_Whi + brow*KPAD_ + bpart*32;
        const __nv_bfloat16* pl = g_Wlo + brow*KPAD_ + bpart*32;
        #pragma unroll
        for (int i = 0; i < 4; i++) {
            pbh[i] = *(const uint4*)(ph + i*8);
            pbl[i] = *(const uint4*)(pl + i*8);
        }
    }

    // A-fill thread mapping
    int fe = tid >> 1;
    int hf = (tid & 1) << 5;          // 0 or 32 (k-half within chunk)
    const float* dist_e = dist_s + fe*25;
    int sde = sd[fe];
    uint32_t aoff = sb + (uint32_t)(fe*SA_ + hf)*2;
    uint32_t boff = sb + (uint32_t)(brow*SA_ + bpart*32)*2;

    #pragma unroll 1
    for (int c = 0; c < NCH_; c++) {
        // ---- store prefetched B chunk ----
        #pragma unroll
        for (int i = 0; i < 4; i++) {
            sts128(boff + SM_BH + i*16, pbh[i].x, pbh[i].y, pbh[i].z, pbh[i].w);
            sts128(boff + SM_BL + i*16, pbl[i].x, pbl[i].y, pbl[i].z, pbl[i].w);
        }
        // ---- prefetch next B chunk (LDG latency hidden by feature build) ----
        if (c + 1 < NCH_) {
            const __nv_bfloat16* ph = g_Whi + brow*KPAD_ + (c+1)*KC_ + bpart*32;
            const __nv_bfloat16* pl = g_Wlo + brow*KPAD_ + (c+1)*KC_ + bpart*32;
            #pragma unroll
            for (int i = 0; i < 4; i++) {
                pbh[i] = *(const uint4*)(ph + i*8);
                pbl[i] = *(const uint4*)(pl + i*8);
            }
        }
        // ---- build A features for this chunk (bf16 hi/lo) ----
        {
            int kg0 = c*KC_ + hf;
            uint32_t hw[16], lw[16];
            #pragma unroll
            for (int u = 0; u < 16; u++) {
                float v0 = featval(kg0 + 2*u,     sde, Wpe_s, bpe_s, dist_e);
                float v1 = featval(kg0 + 2*u + 1, sde, Wpe_s, bpe_s, dist_e);
                __nv_bfloat16 h0 = __float2bfloat16(v0);
                __nv_bfloat16 h1 = __float2bfloat16(v1);
                hw[u] = pk(h0, h1);
                lw[u] = pk(__float2bfloat16(v0 - __bfloat162float(h0)),
                           __float2bfloat16(v1 - __bfloat162float(h1)));
            }
            #pragma unroll
            for (int u4 = 0; u4 < 4; u4++) {
                sts128(aoff + SM_AH + u4*16, hw[4*u4], hw[4*u4+1], hw[4*u4+2], hw[4*u4+3]);
                sts128(aoff + SM_AL + u4*16, lw[4*u4], lw[4*u4+1], lw[4*u4+2], lw[4*u4+3]);
            }
        }
        __syncthreads();

        // ---- 3-pass split HMMA over this chunk ----
        #pragma unroll
        for (int ks = 0; ks < 4; ks++) {
            uint32_t ah[8], al[8];
            ldsm4(ah,     aAh + ks*32);
            ldsm4(ah + 4, aAh + 16*SA_*2 + ks*32);
            ldsm4(al,     aAl + ks*32);
            ldsm4(al + 4, aAl + 16*SA_*2 + ks*32);
            #pragma unroll
            for (int p = 0; p < 4; p++) {
                uint32_t bh[4], bl[4];
                ldsm4(bh, aBh + p*16*SA_*2 + ks*32);
                ldsm4(bl, aBl + p*16*SA_*2 + ks*32);
                #pragma unroll
                for (int mt = 0; mt < 2; mt++) {
                    mma16816(acc[mt][2*p],   ah + 4*mt, bh);
                    mma16816(acc[mt][2*p+1], ah + 4*mt, bh + 2);
                    mma16816(acc[mt][2*p],   ah + 4*mt, bl);
                    mma16816(acc[mt][2*p+1], ah + 4*mt, bl + 2);
                    mma16816(acc[mt][2*p],   al + 4*mt, bh);
                    mma16816(acc[mt][2*p+1], al + 4*mt, bh + 2);
                }
            }
        }
        __syncthreads();   // buffers free for next chunk / stage reuse
    }

    // ---------------- epilogue: LayerNorm + staged store ----------------
    int qrow = lane >> 2;
    #pragma unroll
    for (int mt = 0; mt < 2; mt++) {
        #pragma unroll
        for (int h = 0; h < 2; h++) {
            float s = 0.f, sq = 0.f;
            #pragma unroll
            for (int nt = 0; nt < 8; nt++) {
                float v0 = acc[mt][nt][2*h], v1 = acc[mt][nt][2*h+1];
                s += v0 + v1; sq += v0*v0 + v1*v1;
            }
            s  += __shfl_xor_sync(0xffffffffu, s, 1);
            sq += __shfl_xor_sync(0xffffffffu, sq, 1);
            s  += __shfl_xor_sync(0xffffffffu, s, 2);
            sq += __shfl_xor_sync(0xffffffffu, sq, 2);
            if ((lane & 3) == 0) {
                int row = mw*32 + mt*16 + h*8 + qrow;
                red[row*4 + nw*2 + 0] = s;
                red[row*4 + nw*2 + 1] = sq;
            }
        }
    }
    __syncthreads();

    float* stage = (float*)(smem + SM_STAGE);
    float2 lw2[8], lb2[8];
    int cq = 2*(lane & 3);
    #pragma unroll
    for (int nt = 0; nt < 8; nt++) {
        lw2[nt] = *(float2*)(lnw_s + nw*64 + nt*8 + cq);
        lb2[nt] = *(float2*)(lnb_s + nw*64 + nt*8 + cq);
    }
    #pragma unroll
    for (int mt = 0; mt < 2; mt++) {
        #pragma unroll
        for (int h = 0; h < 2; h++) {
            int row = mw*32 + mt*16 + h*8 + qrow;
            float sum = red[row*4 + 0] + red[row*4 + 2];
            float sq  = red[row*4 + 1] + red[row*4 + 3];
            float mean = sum * (1.0f/128.0f);
            float var  = sq * (1.0f/128.0f) - mean*mean;
            float rstd = rsqrtf(var + 1e-5f);
            float* srow = stage + row*132 + nw*64 + cq;
            #pragma unroll
            for (int nt = 0; nt < 8; nt++) {
                float2 o;
                o.x = (acc[mt][nt][2*h]   - mean)*rstd*lw2[nt].x + lb2[nt].x;
                o.y = (acc[mt][nt][2*h+1] - mean)*rstd*lw2[nt].y + lb2[nt].y;
                *(float2*)(srow + nt*8) = o;
            }
        }
    }
    __syncthreads();

    // coalesced copy stage -> global
    {
        float4* dst = (float4*)(outE + (size_t)blk * EB_ * EF_);
        #pragma unroll 1
        for (int i = tid; i < EB_*EF_/4; i += 256) {
            int row = i >> 5, c4 = i & 31;
            dst[i] = *(float4*)(stage + row*132 + c4*4);
        }
    }
}

// ---------------------------------------------------------------------------
extern "C" void kernel_launch(void* const* d_in, const int* in_sizes, int n_in,
                              void* d_out, int out_size) {
    (void)in_sizes; (void)n_in; (void)out_size;
    const float* X      = (const float*)d_in[0];
    const float* mask   = (const float*)d_in[1];
    const int*   ridx   = (const int*)  d_in[2];
    const int*   clab   = (const int*)  d_in[3];
    const float* W_pe   = (const float*)d_in[4];
    const float* b_pe   = (const float*)d_in[5];
    const float* W_edge = (const float*)d_in[6];
    const float* ln_w   = (const float*)d_in[7];
    const float* ln_b   = (const float*)d_in[8];

    float* out      = (float*)d_out;
    float* outE     = out;                                   // B*L*K*128
    float* outEidxF = out + (size_t)NEDGE * EF_;             // B*L*K (as float)
    float* outX     = outEidxF + (size_t)NEDGE;              // B*L*4*3

    cudaFuncSetAttribute(edge_kernel, cudaFuncAttributeMaxDynamicSharedMemorySize, SMEM_BYTES);

    prep_kernel<<<(B_*L_ + 255)/256, 256>>>(X, outX);
    wt_kernel  <<<(EF_*KPAD_ + 255)/256, 256>>>(W_edge);
    topk_kernel<<<B_*L_, 256>>>(mask, outEidxF);
    edge_kernel<<<NEDGE/EB_, 256, SMEM_BYTES>>>(ridx, clab, W_pe, b_pe, ln_w, ln_b, outE);
}

// round 10
// speedup vs baseline: 1.5793x; 1.0744x over previous
#include <cuda_runtime.h>
#include <cuda_bf16.h>
#include <cstdint>

// ---------------- problem constants ----------------
#define B_    8
#define L_    1024
#define K_    30
#define EF_   128          // EDGE_FEATURES (= N)
#define EIN_  416          // NUM_PE + NUM_RBF*25 (= K)
#define KPAD_ 448          // K padded to 7*64
#define NPE_  16
#define PEC_  66           // 2*MAX_REL+2
#define NEDGE (B_*L_*K_)   // 245760

// ---------------- edge-kernel tiling ----------------
#define EB_   128          // edges per block (= M)
#define KC_   64           // k per chunk
#define NCH_  7            // KPAD_/KC_
#define SA_   72           // smem row stride in bf16 (64 data + 8 pad; LDSM conflict-free)
#define TSZ_  18432        // one tile: 128 rows * SA_ * 2B

// ---------------- scratch (static device globals) ----------------
__device__ float          g_X5[B_*L_*15];
__device__ int            g_Eidx[NEDGE];
__device__ __nv_bfloat16  g_Whi[EF_*KPAD_];   // W_edge hi part, [n][k] k-major, zero-padded
__device__ __nv_bfloat16  g_Wlo[EF_*KPAD_];   // residual part

// ================= helpers =================
__device__ __forceinline__ uint32_t smem_u32(const void* p) {
    uint32_t a;
    asm("{ .reg .u64 t; cvta.to.shared.u64 t, %1; cvt.u32.u64 %0, t; }" : "=r"(a) : "l"(p));
    return a;
}
__device__ __forceinline__ void sts128(uint32_t addr, uint32_t a, uint32_t b, uint32_t c, uint32_t d) {
    asm volatile("st.shared.v4.b32 [%0], {%1,%2,%3,%4};" :: "r"(addr), "r"(a), "r"(b), "r"(c), "r"(d) : "memory");
}
__device__ __forceinline__ void ldsm4(uint32_t* r, uint32_t addr) {
    asm volatile("ldmatrix.sync.aligned.m8n8.x4.shared.b16 {%0,%1,%2,%3}, [%4];"
        : "=r"(r[0]), "=r"(r[1]), "=r"(r[2]), "=r"(r[3]) : "r"(addr));
}
__device__ __forceinline__ void mma16816(float (&d)[4], const uint32_t* a, const uint32_t* b) {
    asm volatile("mma.sync.aligned.m16n8k16.row.col.f32.bf16.bf16.f32 "
        "{%0,%1,%2,%3}, {%4,%5,%6,%7}, {%8,%9}, {%0,%1,%2,%3};"
        : "+f"(d[0]), "+f"(d[1]), "+f"(d[2]), "+f"(d[3])
        : "r"(a[0]), "r"(a[1]), "r"(a[2]), "r"(a[3]), "r"(b[0]), "r"(b[1]));
}
__device__ __forceinline__ uint32_t pk(__nv_bfloat16 a, __nv_bfloat16 b) {
    return (uint32_t)__bfloat16_as_ushort(a) | ((uint32_t)__bfloat16_as_ushort(b) << 16);
}
__device__ __forceinline__ void cpasync16(uint32_t dst, const void* src) {
    asm volatile("cp.async.cg.shared.global [%0], [%1], 16;" :: "r"(dst), "l"(src) : "memory");
}
#define CP_COMMIT() asm volatile("cp.async.commit_group;" ::: "memory")
#define CP_WAIT0()  asm volatile("cp.async.wait_group 0;" ::: "memory")

// ================= kernel 1: build X5 + passthrough X =================
__global__ void prep_kernel(const float* __restrict__ X, float* __restrict__ outX) {
    int t = blockIdx.x * blockDim.x + threadIdx.x;
    if (t >= B_*L_) return;
    const float* x = X + (size_t)t * 12;
    float x0x=x[0], x0y=x[1],  x0z=x[2];
    float x1x=x[3], x1y=x[4],  x1z=x[5];
    float x2x=x[6], x2y=x[7],  x2z=x[8];
    float bx=x1x-x0x, by=x1y-x0y, bz=x1z-x0z;
    float cx=x2x-x1x, cy=x2y-x1y, cz=x2z-x1z;
    float ax=by*cz-bz*cy, ay=bz*cx-bx*cz, az=bx*cy-by*cx;
    float* o = g_X5 + t*15;
    #pragma unroll
    for (int i = 0; i < 12; i++) { o[i] = x[i]; outX[(size_t)t*12 + i] = x[i]; }
    o[12] = -0.58273431f*ax + 0.56802827f*bx - 0.54067466f*cx + x1x;
    o[13] = -0.58273431f*ay + 0.56802827f*by - 0.54067466f*cy + x1y;
    o[14] = -0.58273431f*az + 0.56802827f*bz - 0.54067466f*cz + x1z;
}

// ================= kernel 2: split W_edge into bf16 hi/lo, padded =================
__global__ void wt_kernel(const float* __restrict__ W) {
    int idx = blockIdx.x * blockDim.x + threadIdx.x;
    if (idx >= EF_*KPAD_) return;
    int n = idx / KPAD_, k = idx % KPAD_;
    float w = (k < EIN_) ? W[n*EIN_ + k] : 0.0f;
    __nv_bfloat16 hi = __float2bfloat16(w);
    float lo = w - __bfloat162float(hi);
    g_Whi[idx] = hi;
    g_Wlo[idx] = __float2bfloat16(lo);
}

// ================= kernel 3: per-row distances + stable top-30 =================
__global__ __launch_bounds__(256) void topk_kernel(const float* __restrict__ mask,
                                                   float* __restrict__ outEidxF) {
    __shared__ float sD[L_];
    __shared__ unsigned long long sKey[L_];
    __shared__ float sMaxW[8];
    __shared__ unsigned long long sMinW[8];

    int bi = blockIdx.x;
    int b  = bi >> 10;
    int tid = threadIdx.x, lane = tid & 31, warp = tid >> 5;

    const float* x5b = g_X5 + (size_t)b * L_ * 15;
    int il = bi & (L_-1);
    float cix = x5b[il*15+3], ciy = x5b[il*15+4], ciz = x5b[il*15+5];
    float mi = mask[bi];

    float lmax = -1e30f;
    for (int j = tid; j < L_; j += 256) {
        float dx = cix - x5b[j*15+3];
        float dy = ciy - x5b[j*15+4];
        float dz = ciz - x5b[j*15+5];
        float m2 = mi * mask[b*L_ + j];
        float D  = m2 * sqrtf(dx*dx + dy*dy + dz*dz + 1e-6f);
        sD[j] = D;
        lmax = fmaxf(lmax, D);
    }
    #pragma unroll
    for (int off = 16; off; off >>= 1)
        lmax = fmaxf(lmax, __shfl_xor_sync(0xffffffffu, lmax, off));
    if (lane == 0) sMaxW[warp] = lmax;
    __syncthreads();
    if (tid == 0) {
        float m = sMaxW[0];
        #pragma unroll
        for (int w = 1; w < 8; w++) m = fmaxf(m, sMaxW[w]);
        sMaxW[0] = m;
    }
    __syncthreads();
    float Dmax = sMaxW[0];

    for (int j = tid; j < L_; j += 256) {
        float m2 = mi * mask[b*L_ + j];
        float adj = sD[j] + (1.0f - m2) * Dmax;
        sKey[j] = ((unsigned long long)__float_as_uint(adj) << 32) | (unsigned)j;
    }
    __syncthreads();

    for (int it = 0; it < K_; it++) {
        unsigned long long lm = ~0ull;
        #pragma unroll
        for (int r = 0; r < L_/256; r++) {
            unsigned long long v = sKey[tid + r*256];
            lm = (v < lm) ? v : lm;
        }
        #pragma unroll
        for (int off = 16; off; off >>= 1) {
            unsigned long long v = __shfl_xor_sync(0xffffffffu, lm, off);
            lm = (v < lm) ? v : lm;
        }
        if (lane == 0) sMinW[warp] = lm;
        __syncthreads();
        if (tid == 0) {
            unsigned long long m = sMinW[0];
            #pragma unroll
            for (int w = 1; w < 8; w++) { unsigned long long v = sMinW[w]; m = (v < m) ? v : m; }
            int idx = (int)(m & 0xffffffffu);
            g_Eidx[bi*K_ + it]   = idx;
            outEidxF[bi*K_ + it] = (float)idx;
            sKey[idx] = ~0ull;
        }
        __syncthreads();
    }
}

// ================= kernel 4: HMMA edge kernel (double-buffered) =================
// 128 edges/block, 256 threads. K chunked at 64 (7 chunks), DOUBLE-BUFFERED:
// one __syncthreads per chunk; mma(c) on buf then fill(c+1) into buf^1 so
// warps decouple and ptxas interleaves featval math into HMMA bubbles.
// B (weights hi/lo) arrives via cp.async (no regs, no STS).

// smem offsets (bytes)
#define SM_RED   0        // 2048
#define SM_SD    2048     // 512
#define SM_SI    2560     // 512
#define SM_SN    3072     // 512
#define SM_WPE   3584     // 4224
#define SM_BPE   7808     // 64
#define SM_LNW   7872     // 512
#define SM_LNB   8384     // 512
#define SM_DIST  8896     // 12800 -> 21696
#define SM_TILES 21760    // 8 tiles * 18432 = 147456
// buffer b (0/1): AH = SM_TILES + b*4*TSZ_, AL = +TSZ_, BH = +2*TSZ_, BL = +3*TSZ_
#define SM_STAGE SM_TILES // 128*132*4 = 67584 (reuses tiles post-GEMM)
#define SMEM_BYTES (SM_TILES + 8*TSZ_)   // 169216

__device__ __forceinline__ float featval(int k, int sde,
                                         const float* __restrict__ Wpe_s,
                                         const float* __restrict__ bpe_s,
                                         const float* __restrict__ dist_e) {
    if (k < NPE_) return Wpe_s[k*PEC_ + sde] + bpe_s[k];
    if (k < EIN_) {
        int q = k - NPE_;
        float d = dist_e[q >> 4];
        int m = q & 15;
        float t = (d - (2.0f + 1.33333337f*(float)m)) * 0.8f;
        return __expf(-t*t);
    }
    return 0.0f;
}

__global__ __launch_bounds__(256, 1) void edge_kernel(
    const int*   __restrict__ ridx,
    const int*   __restrict__ clab,
    const float* __restrict__ W_pe,
    const float* __restrict__ b_pe,
    const float* __restrict__ ln_w,
    const float* __restrict__ ln_b,
    float*       __restrict__ outE)
{
    extern __shared__ char smem[];
    uint32_t sb = smem_u32(smem);
    int tid = threadIdx.x, lane = tid & 31, wid = tid >> 5;
    int blk = blockIdx.x;

    float* red    = (float*)(smem + SM_RED);
    int*   sd     = (int*)  (smem + SM_SD);
    int*   sI     = (int*)  (smem + SM_SI);
    int*   sN     = (int*)  (smem + SM_SN);
    float* Wpe_s  = (float*)(smem + SM_WPE);
    float* bpe_s  = (float*)(smem + SM_BPE);
    float* lnw_s  = (float*)(smem + SM_LNW);
    float* lnb_s  = (float*)(smem + SM_LNB);
    float* dist_s = (float*)(smem + SM_DIST);

    // small caches
    for (int i = tid; i < NPE_*PEC_; i += 256) Wpe_s[i] = W_pe[i];
    if (tid < NPE_) bpe_s[tid] = b_pe[tid];
    if (tid < EF_)  { lnw_s[tid] = ln_w[tid]; lnb_s[tid] = ln_b[tid]; }

    // edge metadata + positional-encoding class
    if (tid < EB_) {
        int eg  = blk*EB_ + tid;
        int b   = eg / (L_*K_);
        int r   = eg % (L_*K_);
        int i   = r / K_;
        int nbr = g_Eidx[eg];
        int gi = b*L_ + i, gn = b*L_ + nbr;
        sI[tid] = gi; sN[tid] = gn;
        int off  = ridx[gi] - ridx[gn];
        int same = (clab[gi] == clab[gn]);
        int c = off + 32; c = c < 0 ? 0 : (c > 64 ? 64 : c);
        sd[tid] = same ? c : 65;
    }
    __syncthreads();

    // 25 inter-atom distances per edge
    for (int w = tid; w < EB_*25; w += 256) {
        int e = w / 25, p = w % 25;
        int a = p / 5, bb = p % 5;
        const float* xi = g_X5 + sI[e]*15 + a*3;
        const float* xn = g_X5 + sN[e]*15 + bb*3;
        float dx = xi[0]-xn[0], dy = xi[1]-xn[1], dz = xi[2]-xn[2];
        dist_s[w] = sqrtf(dx*dx + dy*dy + dz*dz + 1e-6f);
    }
    __syncthreads();

    // lane-invariant ldmatrix address components
    int mw = wid >> 1, nw = wid & 1;
    int arow_l = ((lane>>3)&1)*8 + (lane&7);
    int acoff  = (lane>>4)*8;
    int nrow_l = (lane>>4)*8 + (lane&7);
    int bkoff  = ((lane>>3)&1)*8;
    uint32_t aAh0 = sb + SM_TILES + (uint32_t)((mw*32 + arow_l)*SA_ + acoff)*2;
    uint32_t aAl0 = aAh0 + TSZ_;
    uint32_t aBh0 = sb + SM_TILES + 2*TSZ_ + (uint32_t)((nw*64 + nrow_l)*SA_ + bkoff)*2;
    uint32_t aBl0 = aBh0 + TSZ_;

    // A-fill thread mapping
    int fe = tid >> 1;
    int hf = (tid & 1) << 5;          // 0 or 32 (k-half within chunk)
    const float* dist_e = dist_s + fe*25;
    int sde = sd[fe];
    uint32_t aFill0 = sb + SM_TILES + (uint32_t)(fe*SA_ + hf)*2;

    // B cp.async thread mapping: 4 (n,g) pairs per tile per thread
    int bn = tid >> 1;                            // used as i = tid + it*256 -> n = i>>3
    (void)bn;

    float acc[2][8][4];
    #pragma unroll
    for (int mt = 0; mt < 2; mt++)
        #pragma unroll
        for (int nt = 0; nt < 8; nt++)
            #pragma unroll
            for (int i = 0; i < 4; i++) acc[mt][nt][i] = 0.0f;

    // ---- prologue: B0 via cp.async + fill A0 into buffer 0 ----
    {
        uint32_t bh = sb + SM_TILES + 2*TSZ_;
        #pragma unroll
        for (int it = 0; it < 4; it++) {
            int i = tid + it*256;
            int n = i >> 3, g = i & 7;
            uint32_t off = (uint32_t)(n*SA_ + g*8)*2;
            cpasync16(bh + off,        g_Whi + n*KPAD_ + g*8);
            cpasync16(bh + TSZ_ + off, g_Wlo + n*KPAD_ + g*8);
        }
        CP_COMMIT();
        // fill A chunk 0
        uint32_t hw[16], lw[16];
        #pragma unroll
        for (int u = 0; u < 16; u++) {
            float v0 = featval(hf + 2*u,     sde, Wpe_s, bpe_s, dist_e);
            float v1 = featval(hf + 2*u + 1, sde, Wpe_s, bpe_s, dist_e);
            __nv_bfloat16 h0 = __float2bfloat16(v0);
            __nv_bfloat16 h1 = __float2bfloat16(v1);
            hw[u] = pk(h0, h1);
            lw[u] = pk(__float2bfloat16(v0 - __bfloat162float(h0)),
                       __float2bfloat16(v1 - __bfloat162float(h1)));
        }
        #pragma unroll
        for (int u4 = 0; u4 < 4; u4++) {
            sts128(aFill0 + u4*16,        hw[4*u4], hw[4*u4+1], hw[4*u4+2], hw[4*u4+3]);
            sts128(aFill0 + TSZ_ + u4*16, lw[4*u4], lw[4*u4+1], lw[4*u4+2], lw[4*u4+3]);
        }
        CP_WAIT0();
    }
    __syncthreads();

    // ---- main loop: one sync per chunk ----
    #pragma unroll 1
    for (int c = 0; c < NCH_; c++) {
        uint32_t curOff = (uint32_t)(c & 1) * (4*TSZ_);
        uint32_t nxtOff = (uint32_t)((c+1) & 1) * (4*TSZ_);

        // issue cp.async for B(c+1) into next buffer (free since last sync)
        if (c + 1 < NCH_) {
            uint32_t bh = sb + SM_TILES + nxtOff + 2*TSZ_;
            #pragma unroll
            for (int it = 0; it < 4; it++) {
                int i = tid + it*256;
                int n = i >> 3, g = i & 7;
                uint32_t off = (uint32_t)(n*SA_ + g*8)*2;
                cpasync16(bh + off,        g_Whi + n*KPAD_ + (c+1)*KC_ + g*8);
                cpasync16(bh + TSZ_ + off, g_Wlo + n*KPAD_ + (c+1)*KC_ + g*8);
            }
            CP_COMMIT();
        }

        // ---- 3-pass split HMMA on current buffer ----
        uint32_t aAh = aAh0 + curOff, aAl = aAl0 + curOff;
        uint32_t aBh = aBh0 + curOff, aBl = aBl0 + curOff;
        #pragma unroll
        for (int ks = 0; ks < 4; ks++) {
            uint32_t ah[8], al[8];
            ldsm4(ah,     aAh + ks*32);
            ldsm4(ah + 4, aAh + 16*SA_*2 + ks*32);
            ldsm4(al,     aAl + ks*32);
            ldsm4(al + 4, aAl + 16*SA_*2 + ks*32);
            #pragma unroll
            for (int p = 0; p < 4; p++) {
                uint32_t bh[4], bl[4];
                ldsm4(bh, aBh + p*16*SA_*2 + ks*32);
                ldsm4(bl, aBl + p*16*SA_*2 + ks*32);
                #pragma unroll
                for (int mt = 0; mt < 2; mt++) {
                    mma16816(acc[mt][2*p],   ah + 4*mt, bh);
                    mma16816(acc[mt][2*p+1], ah + 4*mt, bh + 2);
                    mma16816(acc[mt][2*p],   ah + 4*mt, bl);
                    mma16816(acc[mt][2*p+1], ah + 4*mt, bl + 2);
                    mma16816(acc[mt][2*p],   al + 4*mt, bh);
                    mma16816(acc[mt][2*p+1], al + 4*mt, bh + 2);
                }
            }
        }

        // ---- fill A(c+1) into next buffer (featval math hides in MMA bubbles) ----
        if (c + 1 < NCH_) {
            int kg0 = (c+1)*KC_ + hf;
            uint32_t aF = aFill0 + nxtOff;
            uint32_t hw[16], lw[16];
            #pragma unroll
            for (int u = 0; u < 16; u++) {
                float v0 = featval(kg0 + 2*u,     sde, Wpe_s, bpe_s, dist_e);
                float v1 = featval(kg0 + 2*u + 1, sde, Wpe_s, bpe_s, dist_e);
                __nv_bfloat16 h0 = __float2bfloat16(v0);
                __nv_bfloat16 h1 = __float2bfloat16(v1);
                hw[u] = pk(h0, h1);
                lw[u] = pk(__float2bfloat16(v0 - __bfloat162float(h0)),
                           __float2bfloat16(v1 - __bfloat162float(h1)));
            }
            #pragma unroll
            for (int u4 = 0; u4 < 4; u4++) {
                sts128(aF + u4*16,        hw[4*u4], hw[4*u4+1], hw[4*u4+2], hw[4*u4+3]);
                sts128(aF + TSZ_ + u4*16, lw[4*u4], lw[4*u4+1], lw[4*u4+2], lw[4*u4+3]);
            }
        }
        CP_WAIT0();
        __syncthreads();
    }

    // ---------------- epilogue: LayerNorm + staged store ----------------
    int qrow = lane >> 2;
    #pragma unroll
    for (int mt = 0; mt < 2; mt++) {
        #pragma unroll
        for (int h = 0; h < 2; h++) {
            float s = 0.f, sq = 0.f;
            #pragma unroll
            for (int nt = 0; nt < 8; nt++) {
                float v0 = acc[mt][nt][2*h], v1 = acc[mt][nt][2*h+1];
                s += v0 + v1; sq += v0*v0 + v1*v1;
            }
            s  += __shfl_xor_sync(0xffffffffu, s, 1);
            sq += __shfl_xor_sync(0xffffffffu, sq, 1);
            s  += __shfl_xor_sync(0xffffffffu, s, 2);
            sq += __shfl_xor_sync(0xffffffffu, sq, 2);
            if ((lane & 3) == 0) {
                int row = mw*32 + mt*16 + h*8 + qrow;
                red[row*4 + nw*2 + 0] = s;
                red[row*4 + nw*2 + 1] = sq;
            }
        }
    }
    __syncthreads();

    float* stage = (float*)(smem + SM_STAGE);
    float2 lw2[8], lb2[8];
    int cq = 2*(lane & 3);
    #pragma unroll
    for (int nt = 0; nt < 8; nt++) {
        lw2[nt] = *(float2*)(lnw_s + nw*64 + nt*8 + cq);
        lb2[nt] = *(float2*)(lnb_s + nw*64 + nt*8 + cq);
    }
    #pragma unroll
    for (int mt = 0; mt < 2; mt++) {
        #pragma unroll
        for (int h = 0; h < 2; h++) {
            int row = mw*32 + mt*16 + h*8 + qrow;
            float sum = red[row*4 + 0] + red[row*4 + 2];
            float sq  = red[row*4 + 1] + red[row*4 + 3];
            float mean = sum * (1.0f/128.0f);
            float var  = sq * (1.0f/128.0f) - mean*mean;
            float rstd = rsqrtf(var + 1e-5f);
            float* srow = stage + row*132 + nw*64 + cq;
            #pragma unroll
            for (int nt = 0; nt < 8; nt++) {
                float2 o;
                o.x = (acc[mt][nt][2*h]   - mean)*rstd*lw2[nt].x + lb2[nt].x;
                o.y = (acc[mt][nt][2*h+1] - mean)*rstd*lw2[nt].y + lb2[nt].y;
                *(float2*)(srow + nt*8) = o;
            }
        }
    }
    __syncthreads();

    // coalesced copy stage -> global
    {
        float4* dst = (float4*)(outE + (size_t)blk * EB_ * EF_);
        #pragma unroll 1
        for (int i = tid; i < EB_*EF_/4; i += 256) {
            int row = i >> 5, c4 = i & 31;
            dst[i] = *(float4*)(stage + row*132 + c4*4);
        }
    }
}

// ---------------------------------------------------------------------------
extern "C" void kernel_launch(void* const* d_in, const int* in_sizes, int n_in,
                              void* d_out, int out_size) {
    (void)in_sizes; (void)n_in; (void)out_size;
    const float* X      = (const float*)d_in[0];
    const float* mask   = (const float*)d_in[1];
    const int*   ridx   = (const int*)  d_in[2];
    const int*   clab   = (const int*)  d_in[3];
    const float* W_pe   = (const float*)d_in[4];
    const float* b_pe   = (const float*)d_in[5];
    const float* W_edge = (const float*)d_in[6];
    const float* ln_w   = (const float*)d_in[7];
    const float* ln_b   = (const float*)d_in[8];

    float* out      = (float*)d_out;
    float* outE     = out;                                   // B*L*K*128
    float* outEidxF = out + (size_t)NEDGE * EF_;             // B*L*K (as float)
    float* outX     = outEidxF + (size_t)NEDGE;              // B*L*4*3

    cudaFuncSetAttribute(edge_kernel, cudaFuncAttributeMaxDynamicSharedMemorySize, SMEM_BYTES);

    prep_kernel<<<(B_*L_ + 255)/256, 256>>>(X, outX);
    wt_kernel  <<<(EF_*KPAD_ + 255)/256, 256>>>(W_edge);
    topk_kernel<<<B_*L_, 256>>>(mask, outEidxF);
    edge_kernel<<<NEDGE/EB_, 256, SMEM_BYTES>>>(ridx, clab, W_pe, b_pe, ln_w, ln_b, outE);
}

// round 11
// speedup vs baseline: 2.0236x; 1.2813x over previous
#include <cuda_runtime.h>
#include <cuda_bf16.h>
#include <cstdint>

// ---------------- problem constants ----------------
#define B_    8
#define L_    1024
#define K_    30
#define EF_   128          // EDGE_FEATURES (= N)
#define EIN_  416          // NUM_PE + NUM_RBF*25 (= K)
#define KPAD_ 448          // K padded to 7*64
#define NPE_  16
#define PEC_  66           // 2*MAX_REL+2
#define NEDGE (B_*L_*K_)   // 245760

// ---------------- edge-kernel tiling ----------------
#define EB_   64           // edges per block (= M)
#define KC_   64           // k per chunk (= 128 bytes/row)
#define NCH_  7            // KPAD_/KC_
#define ATSZ_ 8192         // A tile: 64 rows * 128B
#define BTSZ_ 16384        // B tile: 128 rows * 128B
#define BUFSZ_ (2*ATSZ_ + 2*BTSZ_)   // 49152 per buffer

// ---------------- scratch (static device globals) ----------------
__device__ float          g_X5[B_*L_*15];
__device__ int            g_Eidx[NEDGE];
__device__ __nv_bfloat16  g_Whi[EF_*KPAD_];   // W_edge hi part, [n][k] k-major, zero-padded
__device__ __nv_bfloat16  g_Wlo[EF_*KPAD_];   // residual part

// ================= helpers =================
__device__ __forceinline__ uint32_t smem_u32(const void* p) {
    uint32_t a;
    asm("{ .reg .u64 t; cvta.to.shared.u64 t, %1; cvt.u32.u64 %0, t; }" : "=r"(a) : "l"(p));
    return a;
}
__device__ __forceinline__ void sts128(uint32_t addr, uint32_t a, uint32_t b, uint32_t c, uint32_t d) {
    asm volatile("st.shared.v4.b32 [%0], {%1,%2,%3,%4};" :: "r"(addr), "r"(a), "r"(b), "r"(c), "r"(d) : "memory");
}
__device__ __forceinline__ void ldsm4(uint32_t* r, uint32_t addr) {
    asm volatile("ldmatrix.sync.aligned.m8n8.x4.shared.b16 {%0,%1,%2,%3}, [%4];"
        : "=r"(r[0]), "=r"(r[1]), "=r"(r[2]), "=r"(r[3]) : "r"(addr));
}
__device__ __forceinline__ void mma16816(float (&d)[4], const uint32_t* a, const uint32_t* b) {
    asm volatile("mma.sync.aligned.m16n8k16.row.col.f32.bf16.bf16.f32 "
        "{%0,%1,%2,%3}, {%4,%5,%6,%7}, {%8,%9}, {%0,%1,%2,%3};"
        : "+f"(d[0]), "+f"(d[1]), "+f"(d[2]), "+f"(d[3])
        : "r"(a[0]), "r"(a[1]), "r"(a[2]), "r"(a[3]), "r"(b[0]), "r"(b[1]));
}
__device__ __forceinline__ uint32_t pk(__nv_bfloat16 a, __nv_bfloat16 b) {
    return (uint32_t)__bfloat16_as_ushort(a) | ((uint32_t)__bfloat16_as_ushort(b) << 16);
}
__device__ __forceinline__ void cpasync16(uint32_t dst, const void* src) {
    asm volatile("cp.async.cg.shared.global [%0], [%1], 16;" :: "r"(dst), "l"(src) : "memory");
}
#define CP_COMMIT() asm volatile("cp.async.commit_group;" ::: "memory")
#define CP_WAIT0()  asm volatile("cp.async.wait_group 0;" ::: "memory")

// ================= kernel 1: build X5 + passthrough X =================
__global__ void prep_kernel(const float* __restrict__ X, float* __restrict__ outX) {
    int t = blockIdx.x * blockDim.x + threadIdx.x;
    if (t >= B_*L_) return;
    const float* x = X + (size_t)t * 12;
    float x0x=x[0], x0y=x[1],  x0z=x[2];
    float x1x=x[3], x1y=x[4],  x1z=x[5];
    float x2x=x[6], x2y=x[7],  x2z=x[8];
    float bx=x1x-x0x, by=x1y-x0y, bz=x1z-x0z;
    float cx=x2x-x1x, cy=x2y-x1y, cz=x2z-x1z;
    float ax=by*cz-bz*cy, ay=bz*cx-bx*cz, az=bx*cy-by*cx;
    float* o = g_X5 + t*15;
    #pragma unroll
    for (int i = 0; i < 12; i++) { o[i] = x[i]; outX[(size_t)t*12 + i] = x[i]; }
    o[12] = -0.58273431f*ax + 0.56802827f*bx - 0.54067466f*cx + x1x;
    o[13] = -0.58273431f*ay + 0.56802827f*by - 0.54067466f*cy + x1y;
    o[14] = -0.58273431f*az + 0.56802827f*bz - 0.54067466f*cz + x1z;
}

// ================= kernel 2: split W_edge into bf16 hi/lo, padded =================
__global__ void wt_kernel(const float* __restrict__ W) {
    int idx = blockIdx.x * blockDim.x + threadIdx.x;
    if (idx >= EF_*KPAD_) return;
    int n = idx / KPAD_, k = idx % KPAD_;
    float w = (k < EIN_) ? W[n*EIN_ + k] : 0.0f;
    __nv_bfloat16 hi = __float2bfloat16(w);
    float lo = w - __bfloat162float(hi);
    g_Whi[idx] = hi;
    g_Wlo[idx] = __float2bfloat16(lo);
}

// ================= kernel 3: per-row distances + stable top-30 =================
__global__ __launch_bounds__(256) void topk_kernel(const float* __restrict__ mask,
                                                   float* __restrict__ outEidxF) {
    __shared__ float sD[L_];
    __shared__ unsigned long long sKey[L_];
    __shared__ float sMaxW[8];
    __shared__ unsigned long long sMinW[8];

    int bi = blockIdx.x;
    int b  = bi >> 10;
    int tid = threadIdx.x, lane = tid & 31, warp = tid >> 5;

    const float* x5b = g_X5 + (size_t)b * L_ * 15;
    int il = bi & (L_-1);
    float cix = x5b[il*15+3], ciy = x5b[il*15+4], ciz = x5b[il*15+5];
    float mi = mask[bi];

    float lmax = -1e30f;
    for (int j = tid; j < L_; j += 256) {
        float dx = cix - x5b[j*15+3];
        float dy = ciy - x5b[j*15+4];
        float dz = ciz - x5b[j*15+5];
        float m2 = mi * mask[b*L_ + j];
        float D  = m2 * sqrtf(dx*dx + dy*dy + dz*dz + 1e-6f);
        sD[j] = D;
        lmax = fmaxf(lmax, D);
    }
    #pragma unroll
    for (int off = 16; off; off >>= 1)
        lmax = fmaxf(lmax, __shfl_xor_sync(0xffffffffu, lmax, off));
    if (lane == 0) sMaxW[warp] = lmax;
    __syncthreads();
    if (tid == 0) {
        float m = sMaxW[0];
        #pragma unroll
        for (int w = 1; w < 8; w++) m = fmaxf(m, sMaxW[w]);
        sMaxW[0] = m;
    }
    __syncthreads();
    float Dmax = sMaxW[0];

    for (int j = tid; j < L_; j += 256) {
        float m2 = mi * mask[b*L_ + j];
        float adj = sD[j] + (1.0f - m2) * Dmax;
        sKey[j] = ((unsigned long long)__float_as_uint(adj) << 32) | (unsigned)j;
    }
    __syncthreads();

    for (int it = 0; it < K_; it++) {
        unsigned long long lm = ~0ull;
        #pragma unroll
        for (int r = 0; r < L_/256; r++) {
            unsigned long long v = sKey[tid + r*256];
            lm = (v < lm) ? v : lm;
        }
        #pragma unroll
        for (int off = 16; off; off >>= 1) {
            unsigned long long v = __shfl_xor_sync(0xffffffffu, lm, off);
            lm = (v < lm) ? v : lm;
        }
        if (lane == 0) sMinW[warp] = lm;
        __syncthreads();
        if (tid == 0) {
            unsigned long long m = sMinW[0];
            #pragma unroll
            for (int w = 1; w < 8; w++) { unsigned long long v = sMinW[w]; m = (v < m) ? v : m; }
            int idx = (int)(m & 0xffffffffu);
            g_Eidx[bi*K_ + it]   = idx;
            outEidxF[bi*K_ + it] = (float)idx;
            sKey[idx] = ~0ull;
        }
        __syncthreads();
    }
}

// ================= kernel 4: HMMA edge kernel =================
// 64 edges/block (M=64), 256 threads, 2 CTAs/SM (smem ~110KB, regs <=128).
// XOR-swizzled 128B-row tiles (no padding). Double-buffered, one sync/chunk.
// 8 warps: mw = wid>>1 (m16 tile), nw = wid&1 (n64 half). Per k-step: load
// A hi/lo + all 8 B frags, then 3 passes of 8 independent MMAs (RAW spacing 8).

// smem offsets (bytes)
#define SM_RED   0        // 64*4 floats = 1024
#define SM_SD    1024     // 256
#define SM_SI    1280     // 256
#define SM_SN    1536     // 256
#define SM_WPE   1792     // 4224 -> 6016
#define SM_BPE   6016     // 64
#define SM_LNW   6080     // 512
#define SM_LNB   6592     // 512 -> 7104
#define SM_DIST  7104     // 64*25*4 = 6400 -> 13504
#define SM_TILES 14336    // 2 buffers * 49152 = 98304
// buffer b: AH = SM_TILES + b*BUFSZ_, AL = +ATSZ_, BH = +2*ATSZ_, BL = +2*ATSZ_+BTSZ_
#define SM_STAGE SM_TILES // 64*132*4 = 33792 (reuses tiles post-GEMM)
#define SMEM_BYTES (SM_TILES + 2*BUFSZ_)   // 112640

// swizzled byte offset within a tile: row r, 16B-chunk c (0..7)
#define SWO(r, c) ((uint32_t)((r)*128 + (((c) ^ ((r) & 7)) << 4)))

__device__ __forceinline__ float featval(int k, int sde,
                                         const float* __restrict__ Wpe_s,
                                         const float* __restrict__ bpe_s,
                                         const float* __restrict__ dist_e) {
    if (k < NPE_) return Wpe_s[k*PEC_ + sde] + bpe_s[k];
    if (k < EIN_) {
        int q = k - NPE_;
        float d = dist_e[q >> 4];
        int m = q & 15;
        float t = (d - (2.0f + 1.33333337f*(float)m)) * 0.8f;
        return __expf(-t*t);
    }
    return 0.0f;
}

__global__ __launch_bounds__(256, 2) void edge_kernel(
    const int*   __restrict__ ridx,
    const int*   __restrict__ clab,
    const float* __restrict__ W_pe,
    const float* __restrict__ b_pe,
    const float* __restrict__ ln_w,
    const float* __restrict__ ln_b,
    float*       __restrict__ outE)
{
    extern __shared__ char smem[];
    uint32_t sb = smem_u32(smem);
    int tid = threadIdx.x, lane = tid & 31, wid = tid >> 5;
    int blk = blockIdx.x;

    float* red    = (float*)(smem + SM_RED);
    int*   sd     = (int*)  (smem + SM_SD);
    int*   sI     = (int*)  (smem + SM_SI);
    int*   sN     = (int*)  (smem + SM_SN);
    float* Wpe_s  = (float*)(smem + SM_WPE);
    float* bpe_s  = (float*)(smem + SM_BPE);
    float* lnw_s  = (float*)(smem + SM_LNW);
    float* lnb_s  = (float*)(smem + SM_LNB);
    float* dist_s = (float*)(smem + SM_DIST);

    // small caches
    for (int i = tid; i < NPE_*PEC_; i += 256) Wpe_s[i] = W_pe[i];
    if (tid < NPE_) bpe_s[tid] = b_pe[tid];
    if (tid < EF_)  { lnw_s[tid] = ln_w[tid]; lnb_s[tid] = ln_b[tid]; }

    // edge metadata + positional-encoding class
    if (tid < EB_) {
        int eg  = blk*EB_ + tid;
        int b   = eg / (L_*K_);
        int r   = eg % (L_*K_);
        int i   = r / K_;
        int nbr = g_Eidx[eg];
        int gi = b*L_ + i, gn = b*L_ + nbr;
        sI[tid] = gi; sN[tid] = gn;
        int off  = ridx[gi] - ridx[gn];
        int same = (clab[gi] == clab[gn]);
        int c = off + 32; c = c < 0 ? 0 : (c > 64 ? 64 : c);
        sd[tid] = same ? c : 65;
    }
    __syncthreads();

    // 25 inter-atom distances per edge
    for (int w = tid; w < EB_*25; w += 256) {
        int e = w / 25, p = w % 25;
        int a = p / 5, bb = p % 5;
        const float* xi = g_X5 + sI[e]*15 + a*3;
        const float* xn = g_X5 + sN[e]*15 + bb*3;
        float dx = xi[0]-xn[0], dy = xi[1]-xn[1], dz = xi[2]-xn[2];
        dist_s[w] = sqrtf(dx*dx + dy*dy + dz*dz + 1e-6f);
    }
    __syncthreads();

    // warp layout: mw = m16 tile (0..3), nw = n64 half (0..1)
    int mw = wid >> 1, nw = wid & 1;
    // A ldsm lane mapping (same logical layout as validated R9/R10 kernel)
    int arow   = mw*16 + ((lane>>3)&1)*8 + (lane&7);
    int achunk0 = (lane>>4);            // +2*ks
    uint32_t aRowBase = (uint32_t)(arow*128);
    uint32_t aRS      = (uint32_t)(arow & 7);
    // B ldsm lane mapping
    int nrow_l = (lane>>4)*8 + (lane&7);
    int bchunk0 = ((lane>>3)&1);        // +2*ks
    uint32_t bRowBase = (uint32_t)((nw*64 + nrow_l)*128);   // + p*16*128
    uint32_t bRS      = (uint32_t)(nrow_l & 7);

    // A-fill thread mapping: edge fe, k-quarter q (16 bf16 = 2 chunks)
    int fe = tid >> 2;
    int q  = tid & 3;
    const float* dist_e = dist_s + fe*25;
    int sde = sd[fe];
    uint32_t aFillOff0 = SWO(fe, q*2);
    uint32_t aFillOff1 = SWO(fe, q*2+1);

    float acc[8][4];
    #pragma unroll
    for (int nt = 0; nt < 8; nt++)
        #pragma unroll
        for (int i = 0; i < 4; i++) acc[nt][i] = 0.0f;

    // ---- prologue: B0 via cp.async + fill A0 into buffer 0 ----
    {
        uint32_t bh = sb + SM_TILES + 2*ATSZ_;
        #pragma unroll
        for (int it = 0; it < 4; it++) {
            int i = tid + it*256;
            int n = i >> 3, g = i & 7;
            uint32_t off = SWO(n, g);
            cpasync16(bh + off,         g_Whi + n*KPAD_ + g*8);
            cpasync16(bh + BTSZ_ + off, g_Wlo + n*KPAD_ + g*8);
        }
        CP_COMMIT();
        uint32_t ah = sb + SM_TILES;
        uint32_t hw[8], lw[8];
        #pragma unroll
        for (int u = 0; u < 8; u++) {
            float v0 = featval(q*16 + 2*u,     sde, Wpe_s, bpe_s, dist_e);
            float v1 = featval(q*16 + 2*u + 1, sde, Wpe_s, bpe_s, dist_e);
            __nv_bfloat16 h0 = __float2bfloat16(v0);
            __nv_bfloat16 h1 = __float2bfloat16(v1);
            hw[u] = pk(h0, h1);
            lw[u] = pk(__float2bfloat16(v0 - __bfloat162float(h0)),
                       __float2bfloat16(v1 - __bfloat162float(h1)));
        }
        sts128(ah + aFillOff0,         hw[0], hw[1], hw[2], hw[3]);
        sts128(ah + aFillOff1,         hw[4], hw[5], hw[6], hw[7]);
        sts128(ah + ATSZ_ + aFillOff0, lw[0], lw[1], lw[2], lw[3]);
        sts128(ah + ATSZ_ + aFillOff1, lw[4], lw[5], lw[6], lw[7]);
        CP_WAIT0();
    }
    __syncthreads();

    // ---- main loop: one sync per chunk ----
    #pragma unroll 1
    for (int c = 0; c < NCH_; c++) {
        uint32_t cur = sb + SM_TILES + (uint32_t)(c & 1) * BUFSZ_;
        uint32_t nxt = sb + SM_TILES + (uint32_t)((c+1) & 1) * BUFSZ_;

        // issue cp.async for B(c+1) into next buffer
        if (c + 1 < NCH_) {
            uint32_t bh = nxt + 2*ATSZ_;
            #pragma unroll
            for (int it = 0; it < 4; it++) {
                int i = tid + it*256;
                int n = i >> 3, g = i & 7;
                uint32_t off = SWO(n, g);
                cpasync16(bh + off,         g_Whi + n*KPAD_ + (c+1)*KC_ + g*8);
                cpasync16(bh + BTSZ_ + off, g_Wlo + n*KPAD_ + (c+1)*KC_ + g*8);
            }
            CP_COMMIT();
        }

        // ---- MMAs on current buffer ----
        uint32_t Ah = cur, Al = cur + ATSZ_, Bh = cur + 2*ATSZ_, Bl = Bh + BTSZ_;
        #pragma unroll
        for (int ks = 0; ks < 4; ks++) {
            uint32_t aOff = aRowBase + ((((uint32_t)(2*ks) + achunk0) ^ aRS) << 4);
            uint32_t bOff = bRowBase + ((((uint32_t)(2*ks) + bchunk0) ^ bRS) << 4);
            uint32_t ah[4], al[4], bhf[16], blf[16];
            ldsm4(ah, Ah + aOff);
            ldsm4(al, Al + aOff);
            #pragma unroll
            for (int p = 0; p < 4; p++) {
                ldsm4(bhf + 4*p, Bh + bOff + (uint32_t)(p*16*128));
                ldsm4(blf + 4*p, Bl + bOff + (uint32_t)(p*16*128));
            }
            // pass 1: hi*hi (8 independent MMAs)
            #pragma unroll
            for (int p = 0; p < 4; p++) {
                mma16816(acc[2*p],   ah, bhf + 4*p);
                mma16816(acc[2*p+1], ah, bhf + 4*p + 2);
            }
            // pass 2: lo*hi
            #pragma unroll
            for (int p = 0; p < 4; p++) {
                mma16816(acc[2*p],   al, bhf + 4*p);
                mma16816(acc[2*p+1], al, bhf + 4*p + 2);
            }
            // pass 3: hi*lo
            #pragma unroll
            for (int p = 0; p < 4; p++) {
                mma16816(acc[2*p],   ah, blf + 4*p);
                mma16816(acc[2*p+1], ah, blf + 4*p + 2);
            }
        }

        // ---- fill A(c+1) into next buffer ----
        if (c + 1 < NCH_) {
            int kg0 = (c+1)*KC_ + q*16;
            uint32_t ahn = nxt;
            uint32_t hw[8], lw[8];
            #pragma unroll
            for (int u = 0; u < 8; u++) {
                float v0 = featval(kg0 + 2*u,     sde, Wpe_s, bpe_s, dist_e);
                float v1 = featval(kg0 + 2*u + 1, sde, Wpe_s, bpe_s, dist_e);
                __nv_bfloat16 h0 = __float2bfloat16(v0);
                __nv_bfloat16 h1 = __float2bfloat16(v1);
                hw[u] = pk(h0, h1);
                lw[u] = pk(__float2bfloat16(v0 - __bfloat162float(h0)),
                           __float2bfloat16(v1 - __bfloat162float(h1)));
            }
            sts128(ahn + aFillOff0,         hw[0], hw[1], hw[2], hw[3]);
            sts128(ahn + aFillOff1,         hw[4], hw[5], hw[6], hw[7]);
            sts128(ahn + ATSZ_ + aFillOff0, lw[0], lw[1], lw[2], lw[3]);
            sts128(ahn + ATSZ_ + aFillOff1, lw[4], lw[5], lw[6], lw[7]);
        }
        CP_WAIT0();
        __syncthreads();
    }

    // ---------------- epilogue: LayerNorm + staged store ----------------
    int qrow = lane >> 2;
    #pragma unroll
    for (int h = 0; h < 2; h++) {
        float s = 0.f, sq = 0.f;
        #pragma unroll
        for (int nt = 0; nt < 8; nt++) {
            float v0 = acc[nt][2*h], v1 = acc[nt][2*h+1];
            s += v0 + v1; sq += v0*v0 + v1*v1;
        }
        s  += __shfl_xor_sync(0xffffffffu, s, 1);
        sq += __shfl_xor_sync(0xffffffffu, sq, 1);
        s  += __shfl_xor_sync(0xffffffffu, s, 2);
        sq += __shfl_xor_sync(0xffffffffu, sq, 2);
        if ((lane & 3) == 0) {
            int row = mw*16 + h*8 + qrow;
            red[row*4 + nw*2 + 0] = s;
            red[row*4 + nw*2 + 1] = sq;
        }
    }
    __syncthreads();

    float* stage = (float*)(smem + SM_STAGE);
    float2 lw2[8], lb2[8];
    int cq = 2*(lane & 3);
    #pragma unroll
    for (int nt = 0; nt < 8; nt++) {
        lw2[nt] = *(float2*)(lnw_s + nw*64 + nt*8 + cq);
        lb2[nt] = *(float2*)(lnb_s + nw*64 + nt*8 + cq);
    }
    #pragma unroll
    for (int h = 0; h < 2; h++) {
        int row = mw*16 + h*8 + qrow;
        float sum = red[row*4 + 0] + red[row*4 + 2];
        float sq  = red[row*4 + 1] + red[row*4 + 3];
        float mean = sum * (1.0f/128.0f);
        float var  = sq * (1.0f/128.0f) - mean*mean;
        float rstd = rsqrtf(var + 1e-5f);
        float* srow = stage + row*132 + nw*64 + cq;
        #pragma unroll
        for (int nt = 0; nt < 8; nt++) {
            float2 o;
            o.x = (acc[nt][2*h]   - mean)*rstd*lw2[nt].x + lb2[nt].x;
            o.y = (acc[nt][2*h+1] - mean)*rstd*lw2[nt].y + lb2[nt].y;
            *(float2*)(srow + nt*8) = o;
        }
    }
    __syncthreads();

    // coalesced copy stage -> global
    {
        float4* dst = (float4*)(outE + (size_t)blk * EB_ * EF_);
        #pragma unroll 1
        for (int i = tid; i < EB_*EF_/4; i += 256) {
            int row = i >> 5, c4 = i & 31;
            dst[i] = *(float4*)(stage + row*132 + c4*4);
        }
    }
}

// ---------------------------------------------------------------------------
extern "C" void kernel_launch(void* const* d_in, const int* in_sizes, int n_in,
                              void* d_out, int out_size) {
    (void)in_sizes; (void)n_in; (void)out_size;
    const float* X      = (const float*)d_in[0];
    const float* mask   = (const float*)d_in[1];
    const int*   ridx   = (const int*)  d_in[2];
    const int*   clab   = (const int*)  d_in[3];
    const float* W_pe   = (const float*)d_in[4];
    const float* b_pe   = (const float*)d_in[5];
    const float* W_edge = (const float*)d_in[6];
    const float* ln_w   = (const float*)d_in[7];
    const float* ln_b   = (const float*)d_in[8];

    float* out      = (float*)d_out;
    float* outE     = out;                                   // B*L*K*128
    float* outEidxF = out + (size_t)NEDGE * EF_;             // B*L*K (as float)
    float* outX     = outEidxF + (size_t)NEDGE;              // B*L*4*3

    cudaFuncSetAttribute(edge_kernel, cudaFuncAttributeMaxDynamicSharedMemorySize, SMEM_BYTES);

    prep_kernel<<<(B_*L_ + 255)/256, 256>>>(X, outX);
    wt_kernel  <<<(EF_*KPAD_ + 255)/256, 256>>>(W_edge);
    topk_kernel<<<B_*L_, 256>>>(mask, outEidxF);
    edge_kernel<<<NEDGE/EB_, 256, SMEM_BYTES>>>(ridx, clab, W_pe, b_pe, ln_w, ln_b, outE);
}

// round 12
// speedup vs baseline: 2.2503x; 1.1120x over previous
#include <cuda_runtime.h>
#include <cuda_bf16.h>
#include <cuda_fp16.h>
#include <cstdint>

// ---------------- problem constants ----------------
#define B_    8
#define L_    1024
#define K_    30
#define EF_   128          // EDGE_FEATURES (= N)
#define EIN_  416          // NUM_PE + NUM_RBF*25 (= K)
#define KPAD_ 448          // K padded to 7*64
#define NPE_  16
#define PEC_  66           // 2*MAX_REL+2
#define NEDGE (B_*L_*K_)   // 245760

// ---------------- edge-kernel tiling ----------------
#define EB_   64           // edges per block (= M)
#define KC_   64           // k per chunk (= 128 bytes/row fp16)
#define NCH_  7            // KPAD_/KC_
#define ATSZ_ 8192         // A tile: 64 rows * 128B
#define BTSZ_ 16384        // B tile: 128 rows * 128B
#define BUFSZ_ (2*ATSZ_ + BTSZ_)     // 32768 per buffer (A_hi, A_lo, B)

// ---------------- scratch (static device globals) ----------------
__device__ float  g_X5[B_*L_*15];
__device__ int    g_Eidx[NEDGE];
__device__ __half g_Wh[EF_*KPAD_];   // W_edge fp16, [n][k] k-major, zero-padded

// ================= helpers =================
__device__ __forceinline__ uint32_t smem_u32(const void* p) {
    uint32_t a;
    asm("{ .reg .u64 t; cvta.to.shared.u64 t, %1; cvt.u32.u64 %0, t; }" : "=r"(a) : "l"(p));
    return a;
}
__device__ __forceinline__ void sts128(uint32_t addr, uint32_t a, uint32_t b, uint32_t c, uint32_t d) {
    asm volatile("st.shared.v4.b32 [%0], {%1,%2,%3,%4};" :: "r"(addr), "r"(a), "r"(b), "r"(c), "r"(d) : "memory");
}
__device__ __forceinline__ void ldsm4(uint32_t* r, uint32_t addr) {
    asm volatile("ldmatrix.sync.aligned.m8n8.x4.shared.b16 {%0,%1,%2,%3}, [%4];"
        : "=r"(r[0]), "=r"(r[1]), "=r"(r[2]), "=r"(r[3]) : "r"(addr));
}
__device__ __forceinline__ void mma16816(float (&d)[4], const uint32_t* a, const uint32_t* b) {
    asm volatile("mma.sync.aligned.m16n8k16.row.col.f32.f16.f16.f32 "
        "{%0,%1,%2,%3}, {%4,%5,%6,%7}, {%8,%9}, {%0,%1,%2,%3};"
        : "+f"(d[0]), "+f"(d[1]), "+f"(d[2]), "+f"(d[3])
        : "r"(a[0]), "r"(a[1]), "r"(a[2]), "r"(a[3]), "r"(b[0]), "r"(b[1]));
}
__device__ __forceinline__ uint32_t pk16(__half a, __half b) {
    return (uint32_t)__half_as_ushort(a) | ((uint32_t)__half_as_ushort(b) << 16);
}
__device__ __forceinline__ void cpasync16(uint32_t dst, const void* src) {
    asm volatile("cp.async.cg.shared.global [%0], [%1], 16;" :: "r"(dst), "l"(src) : "memory");
}
#define CP_COMMIT() asm volatile("cp.async.commit_group;" ::: "memory")
#define CP_WAIT0()  asm volatile("cp.async.wait_group 0;" ::: "memory")

// ================= kernel 1: build X5 + passthrough X =================
__global__ void prep_kernel(const float* __restrict__ X, float* __restrict__ outX) {
    int t = blockIdx.x * blockDim.x + threadIdx.x;
    if (t >= B_*L_) return;
    const float* x = X + (size_t)t * 12;
    float x0x=x[0], x0y=x[1],  x0z=x[2];
    float x1x=x[3], x1y=x[4],  x1z=x[5];
    float x2x=x[6], x2y=x[7],  x2z=x[8];
    float bx=x1x-x0x, by=x1y-x0y, bz=x1z-x0z;
    float cx=x2x-x1x, cy=x2y-x1y, cz=x2z-x1z;
    float ax=by*cz-bz*cy, ay=bz*cx-bx*cz, az=bx*cy-by*cx;
    float* o = g_X5 + t*15;
    #pragma unroll
    for (int i = 0; i < 12; i++) { o[i] = x[i]; outX[(size_t)t*12 + i] = x[i]; }
    o[12] = -0.58273431f*ax + 0.56802827f*bx - 0.54067466f*cx + x1x;
    o[13] = -0.58273431f*ay + 0.56802827f*by - 0.54067466f*cy + x1y;
    o[14] = -0.58273431f*az + 0.56802827f*bz - 0.54067466f*cz + x1z;
}

// ================= kernel 2: W_edge -> fp16, padded, k-major =================
__global__ void wt_kernel(const float* __restrict__ W) {
    int idx = blockIdx.x * blockDim.x + threadIdx.x;
    if (idx >= EF_*KPAD_) return;
    int n = idx / KPAD_, k = idx % KPAD_;
    float w = (k < EIN_) ? W[n*EIN_ + k] : 0.0f;
    g_Wh[idx] = __float2half_rn(w);
}

// ================= kernel 3: per-row distances + stable top-30 =================
__global__ __launch_bounds__(256) void topk_kernel(const float* __restrict__ mask,
                                                   float* __restrict__ outEidxF) {
    __shared__ float sD[L_];
    __shared__ unsigned long long sKey[L_];
    __shared__ float sMaxW[8];
    __shared__ unsigned long long sMinW[8];

    int bi = blockIdx.x;
    int b  = bi >> 10;
    int tid = threadIdx.x, lane = tid & 31, warp = tid >> 5;

    const float* x5b = g_X5 + (size_t)b * L_ * 15;
    int il = bi & (L_-1);
    float cix = x5b[il*15+3], ciy = x5b[il*15+4], ciz = x5b[il*15+5];
    float mi = mask[bi];

    float lmax = -1e30f;
    for (int j = tid; j < L_; j += 256) {
        float dx = cix - x5b[j*15+3];
        float dy = ciy - x5b[j*15+4];
        float dz = ciz - x5b[j*15+5];
        float m2 = mi * mask[b*L_ + j];
        float D  = m2 * sqrtf(dx*dx + dy*dy + dz*dz + 1e-6f);
        sD[j] = D;
        lmax = fmaxf(lmax, D);
    }
    #pragma unroll
    for (int off = 16; off; off >>= 1)
        lmax = fmaxf(lmax, __shfl_xor_sync(0xffffffffu, lmax, off));
    if (lane == 0) sMaxW[warp] = lmax;
    __syncthreads();
    if (tid == 0) {
        float m = sMaxW[0];
        #pragma unroll
        for (int w = 1; w < 8; w++) m = fmaxf(m, sMaxW[w]);
        sMaxW[0] = m;
    }
    __syncthreads();
    float Dmax = sMaxW[0];

    for (int j = tid; j < L_; j += 256) {
        float m2 = mi * mask[b*L_ + j];
        float adj = sD[j] + (1.0f - m2) * Dmax;
        sKey[j] = ((unsigned long long)__float_as_uint(adj) << 32) | (unsigned)j;
    }
    __syncthreads();

    for (int it = 0; it < K_; it++) {
        unsigned long long lm = ~0ull;
        #pragma unroll
        for (int r = 0; r < L_/256; r++) {
            unsigned long long v = sKey[tid + r*256];
            lm = (v < lm) ? v : lm;
        }
        #pragma unroll
        for (int off = 16; off; off >>= 1) {
            unsigned long long v = __shfl_xor_sync(0xffffffffu, lm, off);
            lm = (v < lm) ? v : lm;
        }
        if (lane == 0) sMinW[warp] = lm;
        __syncthreads();
        if (tid == 0) {
            unsigned long long m = sMinW[0];
            #pragma unroll
            for (int w = 1; w < 8; w++) { unsigned long long v = sMinW[w]; m = (v < m) ? v : m; }
            int idx = (int)(m & 0xffffffffu);
            g_Eidx[bi*K_ + it]   = idx;
            outEidxF[bi*K_ + it] = (float)idx;
            sKey[idx] = ~0ull;
        }
        __syncthreads();
    }
}

// ================= kernel 4: HMMA edge kernel (fp16 2-pass) =================
// 64 edges/block, 256 threads, 2 CTAs/SM (smem ~81KB). XOR-swizzled 128B rows.
// W in fp16 (unsplit); A split fp16 hi/lo -> 2 MMA passes per k-step.
// Warp layout 2x4: mw = wid>>2 (m32), nw = wid&3 (n32). Per ks: 6 ldsm.x4
// feed 16 independent MMAs. Double-buffered, one __syncthreads per chunk.

// smem offsets (bytes)
#define SM_RED   0        // 64*8 floats = 2048
#define SM_SD    2048     // 256
#define SM_SI    2304     // 256
#define SM_SN    2560     // 256
#define SM_WPE   2816     // 4224 -> 7040
#define SM_BPE   7040     // 64
#define SM_LNW   7104     // 512
#define SM_LNB   7616     // 512 -> 8128
#define SM_DIST  8128     // 6400 -> 14528
#define SM_TILES 15360    // 2 buffers * 32768 = 65536
// buffer b: AH = SM_TILES + b*BUFSZ_, AL = +ATSZ_, B = +2*ATSZ_
#define SM_STAGE SM_TILES // 64*132*4 = 33792 (reuses tiles post-GEMM)
#define SMEM_BYTES (SM_TILES + 2*BUFSZ_)   // 80896

// swizzled byte offset within a tile: row r, 16B-chunk c (0..7)
#define SWO(r, c) ((uint32_t)((r)*128 + (((c) ^ ((r) & 7)) << 4)))

__device__ __forceinline__ float featval(int k, int sde,
                                         const float* __restrict__ Wpe_s,
                                         const float* __restrict__ bpe_s,
                                         const float* __restrict__ dist_e) {
    if (k < NPE_) return Wpe_s[k*PEC_ + sde] + bpe_s[k];
    if (k < EIN_) {
        int q = k - NPE_;
        float d = dist_e[q >> 4];
        int m = q & 15;
        float t = (d - (2.0f + 1.33333337f*(float)m)) * 0.8f;
        return __expf(-t*t);
    }
    return 0.0f;
}

__global__ __launch_bounds__(256, 2) void edge_kernel(
    const int*   __restrict__ ridx,
    const int*   __restrict__ clab,
    const float* __restrict__ W_pe,
    const float* __restrict__ b_pe,
    const float* __restrict__ ln_w,
    const float* __restrict__ ln_b,
    float*       __restrict__ outE)
{
    extern __shared__ char smem[];
    uint32_t sb = smem_u32(smem);
    int tid = threadIdx.x, lane = tid & 31, wid = tid >> 5;
    int blk = blockIdx.x;

    float* red    = (float*)(smem + SM_RED);
    int*   sd     = (int*)  (smem + SM_SD);
    int*   sI     = (int*)  (smem + SM_SI);
    int*   sN     = (int*)  (smem + SM_SN);
    float* Wpe_s  = (float*)(smem + SM_WPE);
    float* bpe_s  = (float*)(smem + SM_BPE);
    float* lnw_s  = (float*)(smem + SM_LNW);
    float* lnb_s  = (float*)(smem + SM_LNB);
    float* dist_s = (float*)(smem + SM_DIST);

    // small caches
    for (int i = tid; i < NPE_*PEC_; i += 256) Wpe_s[i] = W_pe[i];
    if (tid < NPE_) bpe_s[tid] = b_pe[tid];
    if (tid < EF_)  { lnw_s[tid] = ln_w[tid]; lnb_s[tid] = ln_b[tid]; }

    // edge metadata + positional-encoding class
    if (tid < EB_) {
        int eg  = blk*EB_ + tid;
        int b   = eg / (L_*K_);
        int r   = eg % (L_*K_);
        int i   = r / K_;
        int nbr = g_Eidx[eg];
        int gi = b*L_ + i, gn = b*L_ + nbr;
        sI[tid] = gi; sN[tid] = gn;
        int off  = ridx[gi] - ridx[gn];
        int same = (clab[gi] == clab[gn]);
        int c = off + 32; c = c < 0 ? 0 : (c > 64 ? 64 : c);
        sd[tid] = same ? c : 65;
    }
    __syncthreads();

    // 25 inter-atom distances per edge
    for (int w = tid; w < EB_*25; w += 256) {
        int e = w / 25, p = w % 25;
        int a = p / 5, bb = p % 5;
        const float* xi = g_X5 + sI[e]*15 + a*3;
        const float* xn = g_X5 + sN[e]*15 + bb*3;
        float dx = xi[0]-xn[0], dy = xi[1]-xn[1], dz = xi[2]-xn[2];
        dist_s[w] = sqrtf(dx*dx + dy*dy + dz*dz + 1e-6f);
    }
    __syncthreads();

    // warp layout: mw = m32 tile (0..1), nw = n32 window (0..3)
    int mw = wid >> 2, nw = wid & 3;
    // A ldsm lane mapping (row within m32; +mt*16 handled by +2048B)
    int arow    = mw*32 + ((lane>>3)&1)*8 + (lane&7);
    uint32_t achunk0 = (uint32_t)(lane>>4);
    uint32_t aRowBase = (uint32_t)(arow*128);
    uint32_t aRS      = (uint32_t)(arow & 7);
    // B ldsm lane mapping (row within n32 window; +p*16 by +2048B)
    int brow_l  = nw*32 + (lane>>4)*8 + (lane&7);
    uint32_t bchunk0 = (uint32_t)((lane>>3)&1);
    uint32_t bRowBase = (uint32_t)(brow_l*128);
    uint32_t bRS      = (uint32_t)(brow_l & 7);

    // A-fill thread mapping: edge fe, k-quarter q (16 values = 2 chunks)
    int fe = tid >> 2;
    int q  = tid & 3;
    const float* dist_e = dist_s + fe*25;
    int sde = sd[fe];
    uint32_t aFillOff0 = SWO(fe, q*2);
    uint32_t aFillOff1 = SWO(fe, q*2+1);

    float acc[2][4][4];
    #pragma unroll
    for (int mt = 0; mt < 2; mt++)
        #pragma unroll
        for (int nt = 0; nt < 4; nt++)
            #pragma unroll
            for (int i = 0; i < 4; i++) acc[mt][nt][i] = 0.0f;

    // ---- prologue: B0 via cp.async + fill A0 into buffer 0 ----
    {
        uint32_t bh = sb + SM_TILES + 2*ATSZ_;
        #pragma unroll
        for (int it = 0; it < 4; it++) {
            int i = tid + it*256;
            int n = i >> 3, g = i & 7;
            cpasync16(bh + SWO(n, g), g_Wh + n*KPAD_ + g*8);
        }
        CP_COMMIT();
        uint32_t ah = sb + SM_TILES;
        uint32_t hw[8], lw[8];
        #pragma unroll
        for (int u = 0; u < 8; u++) {
            float v0 = featval(q*16 + 2*u,     sde, Wpe_s, bpe_s, dist_e);
            float v1 = featval(q*16 + 2*u + 1, sde, Wpe_s, bpe_s, dist_e);
            __half h0 = __float2half_rn(v0);
            __half h1 = __float2half_rn(v1);
            hw[u] = pk16(h0, h1);
            lw[u] = pk16(__float2half_rn(v0 - __half2float(h0)),
                         __float2half_rn(v1 - __half2float(h1)));
        }
        sts128(ah + aFillOff0,         hw[0], hw[1], hw[2], hw[3]);
        sts128(ah + aFillOff1,         hw[4], hw[5], hw[6], hw[7]);
        sts128(ah + ATSZ_ + aFillOff0, lw[0], lw[1], lw[2], lw[3]);
        sts128(ah + ATSZ_ + aFillOff1, lw[4], lw[5], lw[6], lw[7]);
        CP_WAIT0();
    }
    __syncthreads();

    // ---- main loop: one sync per chunk ----
    #pragma unroll 1
    for (int c = 0; c < NCH_; c++) {
        uint32_t cur = sb + SM_TILES + (uint32_t)(c & 1) * BUFSZ_;
        uint32_t nxt = sb + SM_TILES + (uint32_t)((c+1) & 1) * BUFSZ_;

        // issue cp.async for B(c+1) into next buffer
        if (c + 1 < NCH_) {
            uint32_t bh = nxt + 2*ATSZ_;
            #pragma unroll
            for (int it = 0; it < 4; it++) {
                int i = tid + it*256;
                int n = i >> 3, g = i & 7;
                cpasync16(bh + SWO(n, g), g_Wh + n*KPAD_ + (c+1)*KC_ + g*8);
            }
            CP_COMMIT();
        }

        // ---- 2-pass MMAs on current buffer ----
        uint32_t Ah = cur, Al = cur + ATSZ_, Bt = cur + 2*ATSZ_;
        #pragma unroll
        for (int ks = 0; ks < 4; ks++) {
            uint32_t aOff = aRowBase + ((((uint32_t)(2*ks) + achunk0) ^ aRS) << 4);
            uint32_t bOff = bRowBase + ((((uint32_t)(2*ks) + bchunk0) ^ bRS) << 4);
            uint32_t ah[8], al[8], bf[8];
            ldsm4(ah,     Ah + aOff);            // mt0
            ldsm4(ah + 4, Ah + aOff + 2048);     // mt1 (+16 rows)
            ldsm4(al,     Al + aOff);
            ldsm4(al + 4, Al + aOff + 2048);
            ldsm4(bf,     Bt + bOff);            // nt0, nt1
            ldsm4(bf + 4, Bt + bOff + 2048);     // nt2, nt3 (+16 rows)
            // pass 1: A_hi * W  (8 independent MMAs)
            #pragma unroll
            for (int mt = 0; mt < 2; mt++)
                #pragma unroll
                for (int nt = 0; nt < 4; nt++)
                    mma16816(acc[mt][nt], ah + 4*mt, bf + 2*nt);
            // pass 2: A_lo * W
            #pragma unroll
            for (int mt = 0; mt < 2; mt++)
                #pragma unroll
                for (int nt = 0; nt < 4; nt++)
                    mma16816(acc[mt][nt], al + 4*mt, bf + 2*nt);
        }

        // ---- fill A(c+1) into next buffer ----
        if (c + 1 < NCH_) {
            int kg0 = (c+1)*KC_ + q*16;
            uint32_t ahn = nxt;
            uint32_t hw[8], lw[8];
            #pragma unroll
            for (int u = 0; u < 8; u++) {
                float v0 = featval(kg0 + 2*u,     sde, Wpe_s, bpe_s, dist_e);
                float v1 = featval(kg0 + 2*u + 1, sde, Wpe_s, bpe_s, dist_e);
                __half h0 = __float2half_rn(v0);
                __half h1 = __float2half_rn(v1);
                hw[u] = pk16(h0, h1);
                lw[u] = pk16(__float2half_rn(v0 - __half2float(h0)),
                             __float2half_rn(v1 - __half2float(h1)));
            }
            sts128(ahn + aFillOff0,         hw[0], hw[1], hw[2], hw[3]);
            sts128(ahn + aFillOff1,         hw[4], hw[5], hw[6], hw[7]);
            sts128(ahn + ATSZ_ + aFillOff0, lw[0], lw[1], lw[2], lw[3]);
            sts128(ahn + ATSZ_ + aFillOff1, lw[4], lw[5], lw[6], lw[7]);
        }
        CP_WAIT0();
        __syncthreads();
    }

    // ---------------- epilogue: LayerNorm + staged store ----------------
    int qrow = lane >> 2;
    #pragma unroll
    for (int mt = 0; mt < 2; mt++) {
        #pragma unroll
        for (int h = 0; h < 2; h++) {
            float s = 0.f, sq = 0.f;
            #pragma unroll
            for (int nt = 0; nt < 4; nt++) {
                float v0 = acc[mt][nt][2*h], v1 = acc[mt][nt][2*h+1];
                s += v0 + v1; sq += v0*v0 + v1*v1;
            }
            s  += __shfl_xor_sync(0xffffffffu, s, 1);
            sq += __shfl_xor_sync(0xffffffffu, sq, 1);
            s  += __shfl_xor_sync(0xffffffffu, s, 2);
            sq += __shfl_xor_sync(0xffffffffu, sq, 2);
            if ((lane & 3) == 0) {
                int row = mw*32 + mt*16 + h*8 + qrow;
                red[row*8 + nw*2 + 0] = s;
                red[row*8 + nw*2 + 1] = sq;
            }
        }
    }
    __syncthreads();

    float* stage = (float*)(smem + SM_STAGE);
    float2 lw2[4], lb2[4];
    int cq = 2*(lane & 3);
    #pragma unroll
    for (int nt = 0; nt < 4; nt++) {
        lw2[nt] = *(float2*)(lnw_s + nw*32 + nt*8 + cq);
        lb2[nt] = *(float2*)(lnb_s + nw*32 + nt*8 + cq);
    }
    #pragma unroll
    for (int mt = 0; mt < 2; mt++) {
        #pragma unroll
        for (int h = 0; h < 2; h++) {
            int row = mw*32 + mt*16 + h*8 + qrow;
            float sum = red[row*8 + 0] + red[row*8 + 2] + red[row*8 + 4] + red[row*8 + 6];
            float sq  = red[row*8 + 1] + red[row*8 + 3] + red[row*8 + 5] + red[row*8 + 7];
            float mean = sum * (1.0f/128.0f);
            float var  = sq * (1.0f/128.0f) - mean*mean;
            float rstd = rsqrtf(var + 1e-5f);
            float* srow = stage + row*132 + nw*32 + cq;
            #pragma unroll
            for (int nt = 0; nt < 4; nt++) {
                float2 o;
                o.x = (acc[mt][nt][2*h]   - mean)*rstd*lw2[nt].x + lb2[nt].x;
                o.y = (acc[mt][nt][2*h+1] - mean)*rstd*lw2[nt].y + lb2[nt].y;
                *(float2*)(srow + nt*8) = o;
            }
        }
    }
    __syncthreads();

    // coalesced copy stage -> global
    {
        float4* dst = (float4*)(outE + (size_t)blk * EB_ * EF_);
        #pragma unroll 1
        for (int i = tid; i < EB_*EF_/4; i += 256) {
            int row = i >> 5, c4 = i & 31;
            dst[i] = *(float4*)(stage + row*132 + c4*4);
        }
    }
}

// ---------------------------------------------------------------------------
extern "C" void kernel_launch(void* const* d_in, const int* in_sizes, int n_in,
                              void* d_out, int out_size) {
    (void)in_sizes; (void)n_in; (void)out_size;
    const float* X      = (const float*)d_in[0];
    const float* mask   = (const float*)d_in[1];
    const int*   ridx   = (const int*)  d_in[2];
    const int*   clab   = (const int*)  d_in[3];
    const float* W_pe   = (const float*)d_in[4];
    const float* b_pe   = (const float*)d_in[5];
    const float* W_edge = (const float*)d_in[6];
    const float* ln_w   = (const float*)d_in[7];
    const float* ln_b   = (const float*)d_in[8];

    float* out      = (float*)d_out;
    float* outE     = out;                                   // B*L*K*128
    float* outEidxF = out + (size_t)NEDGE * EF_;             // B*L*K (as float)
    float* outX     = outEidxF + (size_t)NEDGE;              // B*L*4*3

    cudaFuncSetAttribute(edge_kernel, cudaFuncAttributeMaxDynamicSharedMemorySize, SMEM_BYTES);

    prep_kernel<<<(B_*L_ + 255)/256, 256>>>(X, outX);
    wt_kernel  <<<(EF_*KPAD_ + 255)/256, 256>>>(W_edge);
    topk_kernel<<<B_*L_, 256>>>(mask, outEidxF);
    edge_kernel<<<NEDGE/EB_, 256, SMEM_BYTES>>>(ridx, clab, W_pe, b_pe, ln_w, ln_b, outE);
}

// round 13
// speedup vs baseline: 3.3829x; 1.5033x over previous
#include <cuda_runtime.h>
#include <cuda_fp16.h>
#include <cstdint>

// ---------------- problem constants ----------------
#define B_    8
#define L_    1024
#define K_    30
#define EF_   128          // EDGE_FEATURES (= N)
#define EIN_  416          // NUM_PE + NUM_RBF*25 (= K)
#define KPAD_ 448          // K padded to 7*64
#define NPE_  16
#define PEC_  66           // 2*MAX_REL+2
#define NEDGE (B_*L_*K_)   // 245760

// ---------------- edge-kernel tiling ----------------
#define EB_   64           // edges per block (= M)
#define KC_   64           // k per chunk (= 128 bytes/row fp16)
#define NCH_  7            // KPAD_/KC_
#define ATSZ_ 8192         // A tile: 64 rows * 128B
#define BTSZ_ 16384        // B tile: 128 rows * 128B
#define BUFSZ_ (ATSZ_ + BTSZ_)       // 24576 per buffer (A, B)

// ---------------- scratch (static device globals) ----------------
__device__ float  g_X5[B_*L_*15];
__device__ int    g_Eidx[NEDGE];
__device__ __half g_Wh[EF_*KPAD_];   // W_edge fp16, [n][k] k-major, zero-padded

// ================= helpers =================
__device__ __forceinline__ uint32_t smem_u32(const void* p) {
    uint32_t a;
    asm("{ .reg .u64 t; cvta.to.shared.u64 t, %1; cvt.u32.u64 %0, t; }" : "=r"(a) : "l"(p));
    return a;
}
__device__ __forceinline__ void sts128(uint32_t addr, uint32_t a, uint32_t b, uint32_t c, uint32_t d) {
    asm volatile("st.shared.v4.b32 [%0], {%1,%2,%3,%4};" :: "r"(addr), "r"(a), "r"(b), "r"(c), "r"(d) : "memory");
}
__device__ __forceinline__ void ldsm4(uint32_t* r, uint32_t addr) {
    asm volatile("ldmatrix.sync.aligned.m8n8.x4.shared.b16 {%0,%1,%2,%3}, [%4];"
        : "=r"(r[0]), "=r"(r[1]), "=r"(r[2]), "=r"(r[3]) : "r"(addr));
}
__device__ __forceinline__ void mma16816(float (&d)[4], const uint32_t* a, const uint32_t* b) {
    asm volatile("mma.sync.aligned.m16n8k16.row.col.f32.f16.f16.f32 "
        "{%0,%1,%2,%3}, {%4,%5,%6,%7}, {%8,%9}, {%0,%1,%2,%3};"
        : "+f"(d[0]), "+f"(d[1]), "+f"(d[2]), "+f"(d[3])
        : "r"(a[0]), "r"(a[1]), "r"(a[2]), "r"(a[3]), "r"(b[0]), "r"(b[1]));
}
__device__ __forceinline__ uint32_t pkh2(float a, float b) {
    __half2 h = __floats2half2_rn(a, b);    // low = a
    return *(uint32_t*)&h;
}
__device__ __forceinline__ void cpasync16(uint32_t dst, const void* src) {
    asm volatile("cp.async.cg.shared.global [%0], [%1], 16;" :: "r"(dst), "l"(src) : "memory");
}
#define CP_COMMIT() asm volatile("cp.async.commit_group;" ::: "memory")
#define CP_WAIT0()  asm volatile("cp.async.wait_group 0;" ::: "memory")

// ================= kernel 1: build X5 + passthrough X =================
__global__ void prep_kernel(const float* __restrict__ X, float* __restrict__ outX) {
    int t = blockIdx.x * blockDim.x + threadIdx.x;
    if (t >= B_*L_) return;
    const float* x = X + (size_t)t * 12;
    float x0x=x[0], x0y=x[1],  x0z=x[2];
    float x1x=x[3], x1y=x[4],  x1z=x[5];
    float x2x=x[6], x2y=x[7],  x2z=x[8];
    float bx=x1x-x0x, by=x1y-x0y, bz=x1z-x0z;
    float cx=x2x-x1x, cy=x2y-x1y, cz=x2z-x1z;
    float ax=by*cz-bz*cy, ay=bz*cx-bx*cz, az=bx*cy-by*cx;
    float* o = g_X5 + t*15;
    #pragma unroll
    for (int i = 0; i < 12; i++) { o[i] = x[i]; outX[(size_t)t*12 + i] = x[i]; }
    o[12] = -0.58273431f*ax + 0.56802827f*bx - 0.54067466f*cx + x1x;
    o[13] = -0.58273431f*ay + 0.56802827f*by - 0.54067466f*cy + x1y;
    o[14] = -0.58273431f*az + 0.56802827f*bz - 0.54067466f*cz + x1z;
}

// ================= kernel 2: W_edge -> fp16, padded, k-major =================
__global__ void wt_kernel(const float* __restrict__ W) {
    int idx = blockIdx.x * blockDim.x + threadIdx.x;
    if (idx >= EF_*KPAD_) return;
    int n = idx / KPAD_, k = idx % KPAD_;
    float w = (k < EIN_) ? W[n*EIN_ + k] : 0.0f;
    g_Wh[idx] = __float2half_rn(w);
}

// ================= kernel 3: register-resident top-30 =================
// Keys live in 4 regs/thread. Per iteration: warp shfl-reduce of maintained
// local min, 8-wide cross-warp reduce in warp 0, winner thread rescans its
// 4 registers. Stable: u64 key = (f32 bits << 32) | j, ties -> lower j.
__global__ __launch_bounds__(256) void topk_kernel(const float* __restrict__ mask,
                                                   float* __restrict__ outEidxF) {
    __shared__ float sMaxW[8];
    __shared__ unsigned long long sW[8];
    __shared__ unsigned long long sWin;

    int bi = blockIdx.x;
    int b  = bi >> 10;
    int tid = threadIdx.x, lane = tid & 31, warp = tid >> 5;

    const float* x5b = g_X5 + (size_t)b * L_ * 15;
    int il = bi & (L_-1);
    float cix = x5b[il*15+3], ciy = x5b[il*15+4], ciz = x5b[il*15+5];
    float mi = mask[bi];

    float Dv[4], m2v[4];
    float lmax = -1e30f;
    #pragma unroll
    for (int r = 0; r < 4; r++) {
        int j = tid + r*256;
        float dx = cix - x5b[j*15+3];
        float dy = ciy - x5b[j*15+4];
        float dz = ciz - x5b[j*15+5];
        float m2 = mi * mask[b*L_ + j];
        float D  = m2 * sqrtf(dx*dx + dy*dy + dz*dz + 1e-6f);
        Dv[r] = D; m2v[r] = m2;
        lmax = fmaxf(lmax, D);
    }
    #pragma unroll
    for (int off = 16; off; off >>= 1)
        lmax = fmaxf(lmax, __shfl_xor_sync(0xffffffffu, lmax, off));
    if (lane == 0) sMaxW[warp] = lmax;
    __syncthreads();
    if (tid == 0) {
        float m = sMaxW[0];
        #pragma unroll
        for (int w = 1; w < 8; w++) m = fmaxf(m, sMaxW[w]);
        sMaxW[0] = m;
    }
    __syncthreads();
    float Dmax = sMaxW[0];

    unsigned long long keys[4];
    #pragma unroll
    for (int r = 0; r < 4; r++) {
        float adj = Dv[r] + (1.0f - m2v[r]) * Dmax;
        keys[r] = ((unsigned long long)__float_as_uint(adj) << 32) | (unsigned)(tid + r*256);
    }
    unsigned long long lm = keys[0];
    #pragma unroll
    for (int r = 1; r < 4; r++) lm = keys[r] < lm ? keys[r] : lm;

    #pragma unroll 1
    for (int it = 0; it < K_; it++) {
        unsigned long long w = lm;
        #pragma unroll
        for (int off = 16; off; off >>= 1) {
            unsigned long long v = __shfl_xor_sync(0xffffffffu, w, off);
            w = v < w ? v : w;
        }
        if (lane == 0) sW[warp] = w;
        __syncthreads();
        if (warp == 0) {
            unsigned long long v = sW[lane & 7];
            #pragma unroll
            for (int off = 4; off; off >>= 1) {
                unsigned long long o = __shfl_xor_sync(0xffffffffu, v, off);
                v = o < v ? o : v;
            }
            if (lane == 0) sWin = v;
        }
        __syncthreads();
        unsigned long long win = sWin;
        if (tid == 0) {
            int idx = (int)(win & 0xffffffffu);
            g_Eidx[bi*K_ + it]   = idx;
            outEidxF[bi*K_ + it] = (float)idx;
        }
        if ((((unsigned)win) & 255u) == (unsigned)tid) {
            int r = (int)((((unsigned)win) >> 8) & 3u);
            keys[r] = ~0ull;
            lm = keys[0];
            #pragma unroll
            for (int rr = 1; rr < 4; rr++) lm = keys[rr] < lm ? keys[rr] : lm;
        }
    }
}

// ================= kernel 4: HMMA edge kernel (fp16 single-pass) =================
// 64 edges/block, 256 threads, 3 CTAs/SM (smem ~63KB). XOR-swizzled 128B rows.
// A and W both fp16 (single MMA pass; error budget validated at 2.15e-4 for W,
// predict ~3e-4 with A added). RBF exps via geometric recurrence (2 MUFU per
// 16 values). Double-buffered, one __syncthreads per chunk.

// smem offsets (bytes)
#define SM_RED   0        // 64*8 floats = 2048
#define SM_SD    2048     // 256
#define SM_SI    2304     // 256
#define SM_SN    2560     // 256
#define SM_WPE   2816     // 4224 -> 7040
#define SM_BPE   7040     // 64
#define SM_LNW   7104     // 512
#define SM_LNB   7616     // 512 -> 8128
#define SM_DIST  8128     // 6400 -> 14528
#define SM_TILES 15360    // 2 buffers * 24576 = 49152
#define SM_STAGE SM_TILES // 64*132*4 = 33792 (reuses tiles post-GEMM)
#define SMEM_BYTES (SM_TILES + 2*BUFSZ_)   // 64512

// swizzled byte offset within a tile: row r, 16B-chunk c (0..7)
#define SWO(r, c) ((uint32_t)((r)*128 + (((c) ^ ((r) & 7)) << 4)))

// Generate the 16 feature values for pair-block pr (pr<0: PE features,
// pr in [0,25): one atom-pair's 16 RBFs via geometric recurrence, else 0).
__device__ __forceinline__ void gen16(int pr, int sde,
                                      const float* __restrict__ Wpe_s,
                                      const float* __restrict__ bpe_s,
                                      const float* __restrict__ dist_e,
                                      float* v) {
    if (pr < 0) {
        #pragma unroll
        for (int u = 0; u < 16; u++) v[u] = Wpe_s[u*PEC_ + sde] + bpe_s[u];
    } else if (pr < 25) {
        const float s  = 1.06666672f;      // 0.8 * 20/15
        const float s2 = 1.13777781f;      // s^2
        const float cc = 0.10273956f;      // exp(-2*s^2)
        float d = dist_e[pr];
        if (d < 12.5f) {
            float t0 = (d - 2.0f) * 0.8f;
            float e = __expf(-t0*t0);
            float r = __expf(2.0f*s*t0 - s2);
            v[0] = e;
            #pragma unroll
            for (int m = 1; m < 16; m++) { e *= r; r *= cc; v[m] = e; }
        } else {
            float t15 = (d - 22.0f) * 0.8f;
            float e = __expf(-t15*t15);
            float sg = __expf(-2.0f*s*t15 - s2);
            v[15] = e;
            #pragma unroll
            for (int m = 14; m >= 0; m--) { e *= sg; sg *= cc; v[m] = e; }
        }
    } else {
        #pragma unroll
        for (int u = 0; u < 16; u++) v[u] = 0.0f;
    }
}

__global__ __launch_bounds__(256, 3) void edge_kernel(
    const int*   __restrict__ ridx,
    const int*   __restrict__ clab,
    const float* __restrict__ W_pe,
    const float* __restrict__ b_pe,
    const float* __restrict__ ln_w,
    const float* __restrict__ ln_b,
    float*       __restrict__ outE)
{
    extern __shared__ char smem[];
    uint32_t sb = smem_u32(smem);
    int tid = threadIdx.x, lane = tid & 31, wid = tid >> 5;
    int blk = blockIdx.x;

    float* red    = (float*)(smem + SM_RED);
    int*   sd     = (int*)  (smem + SM_SD);
    int*   sI     = (int*)  (smem + SM_SI);
    int*   sN     = (int*)  (smem + SM_SN);
    float* Wpe_s  = (float*)(smem + SM_WPE);
    float* bpe_s  = (float*)(smem + SM_BPE);
    float* lnw_s  = (float*)(smem + SM_LNW);
    float* lnb_s  = (float*)(smem + SM_LNB);
    float* dist_s = (float*)(smem + SM_DIST);

    // small caches
    for (int i = tid; i < NPE_*PEC_; i += 256) Wpe_s[i] = W_pe[i];
    if (tid < NPE_) bpe_s[tid] = b_pe[tid];
    if (tid < EF_)  { lnw_s[tid] = ln_w[tid]; lnb_s[tid] = ln_b[tid]; }

    // edge metadata + positional-encoding class
    if (tid < EB_) {
        int eg  = blk*EB_ + tid;
        int b   = eg / (L_*K_);
        int r   = eg % (L_*K_);
        int i   = r / K_;
        int nbr = g_Eidx[eg];
        int gi = b*L_ + i, gn = b*L_ + nbr;
        sI[tid] = gi; sN[tid] = gn;
        int off  = ridx[gi] - ridx[gn];
        int same = (clab[gi] == clab[gn]);
        int c = off + 32; c = c < 0 ? 0 : (c > 64 ? 64 : c);
        sd[tid] = same ? c : 65;
    }
    __syncthreads();

    // 25 inter-atom distances per edge
    for (int w = tid; w < EB_*25; w += 256) {
        int e = w / 25, p = w % 25;
        int a = p / 5, bb = p % 5;
        const float* xi = g_X5 + sI[e]*15 + a*3;
        const float* xn = g_X5 + sN[e]*15 + bb*3;
        float dx = xi[0]-xn[0], dy = xi[1]-xn[1], dz = xi[2]-xn[2];
        dist_s[w] = sqrtf(dx*dx + dy*dy + dz*dz + 1e-6f);
    }
    __syncthreads();

    // warp layout: mw = m32 tile (0..1), nw = n32 window (0..3)
    int mw = wid >> 2, nw = wid & 3;
    int arow    = mw*32 + ((lane>>3)&1)*8 + (lane&7);
    uint32_t achunk0 = (uint32_t)(lane>>4);
    uint32_t aRowBase = (uint32_t)(arow*128);
    uint32_t aRS      = (uint32_t)(arow & 7);
    int brow_l  = nw*32 + (lane>>4)*8 + (lane&7);
    uint32_t bchunk0 = (uint32_t)((lane>>3)&1);
    uint32_t bRowBase = (uint32_t)(brow_l*128);
    uint32_t bRS      = (uint32_t)(brow_l & 7);

    // A-fill thread mapping: edge fe, k-quarter q (16 values = 2 chunks)
    int fe = tid >> 2;
    int q  = tid & 3;
    const float* dist_e = dist_s + fe*25;
    int sde = sd[fe];
    uint32_t aFillOff0 = SWO(fe, q*2);
    uint32_t aFillOff1 = SWO(fe, q*2+1);

    float acc[2][4][4];
    #pragma unroll
    for (int mt = 0; mt < 2; mt++)
        #pragma unroll
        for (int nt = 0; nt < 4; nt++)
            #pragma unroll
            for (int i = 0; i < 4; i++) acc[mt][nt][i] = 0.0f;

    // ---- prologue: B0 via cp.async + fill A0 into buffer 0 ----
    {
        uint32_t bt = sb + SM_TILES + ATSZ_;
        #pragma unroll
        for (int it = 0; it < 4; it++) {
            int i = tid + it*256;
            int n = i >> 3, g = i & 7;
            cpasync16(bt + SWO(n, g), g_Wh + n*KPAD_ + g*8);
        }
        CP_COMMIT();
        float v[16];
        gen16(q - 1, sde, Wpe_s, bpe_s, dist_e, v);
        uint32_t hw[8];
        #pragma unroll
        for (int u = 0; u < 8; u++) hw[u] = pkh2(v[2*u], v[2*u+1]);
        uint32_t ah = sb + SM_TILES;
        sts128(ah + aFillOff0, hw[0], hw[1], hw[2], hw[3]);
        sts128(ah + aFillOff1, hw[4], hw[5], hw[6], hw[7]);
        CP_WAIT0();
    }
    __syncthreads();

    // ---- main loop: one sync per chunk ----
    #pragma unroll 1
    for (int c = 0; c < NCH_; c++) {
        uint32_t cur = sb + SM_TILES + (uint32_t)(c & 1) * BUFSZ_;
        uint32_t nxt = sb + SM_TILES + (uint32_t)((c+1) & 1) * BUFSZ_;

        // issue cp.async for B(c+1) into next buffer
        if (c + 1 < NCH_) {
            uint32_t bt = nxt + ATSZ_;
            #pragma unroll
            for (int it = 0; it < 4; it++) {
                int i = tid + it*256;
                int n = i >> 3, g = i & 7;
                cpasync16(bt + SWO(n, g), g_Wh + n*KPAD_ + (c+1)*KC_ + g*8);
            }
            CP_COMMIT();
        }

        // ---- single-pass MMAs on current buffer ----
        uint32_t At = cur, Bt = cur + ATSZ_;
        #pragma unroll
        for (int ks = 0; ks < 4; ks++) {
            uint32_t aOff = aRowBase + ((((uint32_t)(2*ks) + achunk0) ^ aRS) << 4);
            uint32_t bOff = bRowBase + ((((uint32_t)(2*ks) + bchunk0) ^ bRS) << 4);
            uint32_t ah[8], bf[8];
            ldsm4(ah,     At + aOff);            // mt0
            ldsm4(ah + 4, At + aOff + 2048);     // mt1 (+16 rows)
            ldsm4(bf,     Bt + bOff);            // nt0, nt1
            ldsm4(bf + 4, Bt + bOff + 2048);     // nt2, nt3 (+16 rows)
            #pragma unroll
            for (int mt = 0; mt < 2; mt++)
                #pragma unroll
                for (int nt = 0; nt < 4; nt++)
                    mma16816(acc[mt][nt], ah + 4*mt, bf + 2*nt);
        }

        // ---- fill A(c+1) into next buffer ----
        if (c + 1 < NCH_) {
            float v[16];
            gen16(4*(c+1) + q - 1, sde, Wpe_s, bpe_s, dist_e, v);
            uint32_t hw[8];
            #pragma unroll
            for (int u = 0; u < 8; u++) hw[u] = pkh2(v[2*u], v[2*u+1]);
            sts128(nxt + aFillOff0, hw[0], hw[1], hw[2], hw[3]);
            sts128(nxt + aFillOff1, hw[4], hw[5], hw[6], hw[7]);
        }
        CP_WAIT0();
        __syncthreads();
    }

    // ---------------- epilogue: LayerNorm + staged store ----------------
    int qrow = lane >> 2;
    #pragma unroll
    for (int mt = 0; mt < 2; mt++) {
        #pragma unroll
        for (int h = 0; h < 2; h++) {
            float s = 0.f, sq = 0.f;
            #pragma unroll
            for (int nt = 0; nt < 4; nt++) {
                float v0 = acc[mt][nt][2*h], v1 = acc[mt][nt][2*h+1];
                s += v0 + v1; sq += v0*v0 + v1*v1;
            }
            s  += __shfl_xor_sync(0xffffffffu, s, 1);
            sq += __shfl_xor_sync(0xffffffffu, sq, 1);
            s  += __shfl_xor_sync(0xffffffffu, s, 2);
            sq += __shfl_xor_sync(0xffffffffu, sq, 2);
            if ((lane & 3) == 0) {
                int row = mw*32 + mt*16 + h*8 + qrow;
                red[row*8 + nw*2 + 0] = s;
                red[row*8 + nw*2 + 1] = sq;
            }
        }
    }
    __syncthreads();

    float* stage = (float*)(smem + SM_STAGE);
    float2 lw2[4], lb2[4];
    int cq = 2*(lane & 3);
    #pragma unroll
    for (int nt = 0; nt < 4; nt++) {
        lw2[nt] = *(float2*)(lnw_s + nw*32 + nt*8 + cq);
        lb2[nt] = *(float2*)(lnb_s + nw*32 + nt*8 + cq);
    }
    #pragma unroll
    for (int mt = 0; mt < 2; mt++) {
        #pragma unroll
        for (int h = 0; h < 2; h++) {
            int row = mw*32 + mt*16 + h*8 + qrow;
            float sum = red[row*8 + 0] + red[row*8 + 2] + red[row*8 + 4] + red[row*8 + 6];
            float sq  = red[row*8 + 1] + red[row*8 + 3] + red[row*8 + 5] + red[row*8 + 7];
            float mean = sum * (1.0f/128.0f);
            float var  = sq * (1.0f/128.0f) - mean*mean;
            float rstd = rsqrtf(var + 1e-5f);
            float* srow = stage + row*132 + nw*32 + cq;
            #pragma unroll
            for (int nt = 0; nt < 4; nt++) {
                float2 o;
                o.x = (acc[mt][nt][2*h]   - mean)*rstd*lw2[nt].x + lb2[nt].x;
                o.y = (acc[mt][nt][2*h+1] - mean)*rstd*lw2[nt].y + lb2[nt].y;
                *(float2*)(srow + nt*8) = o;
            }
        }
    }
    __syncthreads();

    // coalesced copy stage -> global
    {
        float4* dst = (float4*)(outE + (size_t)blk * EB_ * EF_);
        #pragma unroll 1
        for (int i = tid; i < EB_*EF_/4; i += 256) {
            int row = i >> 5, c4 = i & 31;
            dst[i] = *(float4*)(stage + row*132 + c4*4);
        }
    }
}

// ---------------------------------------------------------------------------
extern "C" void kernel_launch(void* const* d_in, const int* in_sizes, int n_in,
                              void* d_out, int out_size) {
    (void)in_sizes; (void)n_in; (void)out_size;
    const float* X      = (const float*)d_in[0];
    const float* mask   = (const float*)d_in[1];
    const int*   ridx   = (const int*)  d_in[2];
    const int*   clab   = (const int*)  d_in[3];
    const float* W_pe   = (const float*)d_in[4];
    const float* b_pe   = (const float*)d_in[5];
    const float* W_edge = (const float*)d_in[6];
    const float* ln_w   = (const float*)d_in[7];
    const float* ln_b   = (const float*)d_in[8];

    float* out      = (float*)d_out;
    float* outE     = out;                                   // B*L*K*128
    float* outEidxF = out + (size_t)NEDGE * EF_;             // B*L*K (as float)
    float* outX     = outEidxF + (size_t)NEDGE;              // B*L*4*3

    cudaFuncSetAttribute(edge_kernel, cudaFuncAttributeMaxDynamicSharedMemorySize, SMEM_BYTES);

    prep_kernel<<<(B_*L_ + 255)/256, 256>>>(X, outX);
    wt_kernel  <<<(EF_*KPAD_ + 255)/256, 256>>>(W_edge);
    topk_kernel<<<B_*L_, 256>>>(mask, outEidxF);
    edge_kernel<<<NEDGE/EB_, 256, SMEM_BYTES>>>(ridx, clab, W_pe, b_pe, ln_w, ln_b, outE);
}

// round 14
// speedup vs baseline: 4.6905x; 1.3865x over previous
#include <cuda_runtime.h>
#include <cuda_fp16.h>
#include <cstdint>

// ---------------- problem constants ----------------
#define B_    8
#define L_    1024
#define K_    30
#define EF_   128          // EDGE_FEATURES (= N)
#define EIN_  416          // NUM_PE + NUM_RBF*25 (= K)
#define KPAD_ 448          // K padded to 7*64
#define NPE_  16
#define PEC_  66           // 2*MAX_REL+2
#define NEDGE (B_*L_*K_)   // 245760

// ---------------- edge-kernel tiling ----------------
#define EB_   64           // edges per block (= M)
#define KC_   64           // k per chunk (= 128 bytes/row fp16)
#define NCH_  7            // KPAD_/KC_
#define ATSZ_ 8192         // A tile: 64 rows * 128B
#define BTSZ_ 16384        // B tile: 128 rows * 128B
#define BUFSZ_ (ATSZ_ + BTSZ_)       // 24576 per buffer (A, B)

// ---------------- scratch (static device globals) ----------------
__device__ float  g_X5[B_*L_*15];
__device__ int    g_Eidx[NEDGE];
__device__ __half g_Wh[EF_*KPAD_];   // W_edge fp16, [n][k] k-major, zero-padded

// ================= helpers =================
__device__ __forceinline__ uint32_t smem_u32(const void* p) {
    uint32_t a;
    asm("{ .reg .u64 t; cvta.to.shared.u64 t, %1; cvt.u32.u64 %0, t; }" : "=r"(a) : "l"(p));
    return a;
}
__device__ __forceinline__ void sts128(uint32_t addr, uint32_t a, uint32_t b, uint32_t c, uint32_t d) {
    asm volatile("st.shared.v4.b32 [%0], {%1,%2,%3,%4};" :: "r"(addr), "r"(a), "r"(b), "r"(c), "r"(d) : "memory");
}
__device__ __forceinline__ void ldsm4(uint32_t* r, uint32_t addr) {
    asm volatile("ldmatrix.sync.aligned.m8n8.x4.shared.b16 {%0,%1,%2,%3}, [%4];"
        : "=r"(r[0]), "=r"(r[1]), "=r"(r[2]), "=r"(r[3]) : "r"(addr));
}
__device__ __forceinline__ void mma16816(float (&d)[4], const uint32_t* a, const uint32_t* b) {
    asm volatile("mma.sync.aligned.m16n8k16.row.col.f32.f16.f16.f32 "
        "{%0,%1,%2,%3}, {%4,%5,%6,%7}, {%8,%9}, {%0,%1,%2,%3};"
        : "+f"(d[0]), "+f"(d[1]), "+f"(d[2]), "+f"(d[3])
        : "r"(a[0]), "r"(a[1]), "r"(a[2]), "r"(a[3]), "r"(b[0]), "r"(b[1]));
}
__device__ __forceinline__ uint32_t pkh2(float a, float b) {
    __half2 h = __floats2half2_rn(a, b);    // low = a
    return *(uint32_t*)&h;
}
__device__ __forceinline__ void cpasync16(uint32_t dst, const void* src) {
    asm volatile("cp.async.cg.shared.global [%0], [%1], 16;" :: "r"(dst), "l"(src) : "memory");
}
#define CP_COMMIT() asm volatile("cp.async.commit_group;" ::: "memory")
#define CP_WAIT0()  asm volatile("cp.async.wait_group 0;" ::: "memory")

// ================= kernel 1: fused X5 build + X passthrough + W->fp16 =================
__global__ void prep_kernel(const float* __restrict__ X, const float* __restrict__ W,
                            float* __restrict__ outX) {
    int t = blockIdx.x * blockDim.x + threadIdx.x;
    if (t < B_*L_) {
        const float* x = X + (size_t)t * 12;
        float x0x=x[0], x0y=x[1],  x0z=x[2];
        float x1x=x[3], x1y=x[4],  x1z=x[5];
        float x2x=x[6], x2y=x[7],  x2z=x[8];
        float bx=x1x-x0x, by=x1y-x0y, bz=x1z-x0z;
        float cx=x2x-x1x, cy=x2y-x1y, cz=x2z-x1z;
        float ax=by*cz-bz*cy, ay=bz*cx-bx*cz, az=bx*cy-by*cx;
        float* o = g_X5 + t*15;
        #pragma unroll
        for (int i = 0; i < 12; i++) { o[i] = x[i]; outX[(size_t)t*12 + i] = x[i]; }
        o[12] = -0.58273431f*ax + 0.56802827f*bx - 0.54067466f*cx + x1x;
        o[13] = -0.58273431f*ay + 0.56802827f*by - 0.54067466f*cy + x1y;
        o[14] = -0.58273431f*az + 0.56802827f*bz - 0.54067466f*cz + x1z;
    }
    if (t < EF_*KPAD_) {
        int n = t / KPAD_, k = t % KPAD_;
        float w = (k < EIN_) ? W[n*EIN_ + k] : 0.0f;
        g_Wh[t] = __float2half_rn(w);
    }
}

// ================= kernel 2: radix-select top-30 =================
// One block per (b,i). Single histogram pass over float-bit bins [30:19]
// (4096 bins), prefix scan locates the rank-30 bin, then rank the small
// candidate set (definite < bin, ties == bin) by counting-smaller.
// u64 key = (f32 bits << 32) | j keeps exact lax.top_k order (ties -> low j).
#define NBIN_ 4096
__global__ __launch_bounds__(256) void topk_kernel(const float* __restrict__ X,
                                                   const float* __restrict__ mask,
                                                   float* __restrict__ outEidxF) {
    __shared__ unsigned int hist[NBIN_];       // 16 KB
    __shared__ float sMaxW[8];
    __shared__ int   sWS[8];
    __shared__ int   sT, sCnt[2];              // threshold bin; def/tie counters
    __shared__ unsigned long long defL[32];
    __shared__ unsigned long long tieL[320];

    int bi = blockIdx.x;
    int b  = bi >> 10;
    int tid = threadIdx.x, lane = tid & 31, warp = tid >> 5;

    const float* xb = X + (size_t)b * L_ * 12;   // Ca = atom 1 of X directly
    int il = bi & (L_-1);
    float cix = xb[il*12+3], ciy = xb[il*12+4], ciz = xb[il*12+5];
    float mi = mask[bi];

    float Dv[4], m2v[4];
    float lmax = -1e30f;
    #pragma unroll
    for (int r = 0; r < 4; r++) {
        int j = tid + r*256;
        float dx = cix - xb[j*12+3];
        float dy = ciy - xb[j*12+4];
        float dz = ciz - xb[j*12+5];
        float m2 = mi * mask[b*L_ + j];
        float D  = m2 * sqrtf(dx*dx + dy*dy + dz*dz + 1e-6f);
        Dv[r] = D; m2v[r] = m2;
        lmax = fmaxf(lmax, D);
    }
    #pragma unroll
    for (int off = 16; off; off >>= 1)
        lmax = fmaxf(lmax, __shfl_xor_sync(0xffffffffu, lmax, off));
    if (lane == 0) sMaxW[warp] = lmax;

    // zero histogram + counters while max lands
    #pragma unroll
    for (int u = 0; u < NBIN_/256; u++) hist[tid + u*256] = 0;
    if (tid == 0) { sCnt[0] = 0; sCnt[1] = 0; }
    __syncthreads();
    if (tid == 0) {
        float m = sMaxW[0];
        #pragma unroll
        for (int w = 1; w < 8; w++) m = fmaxf(m, sMaxW[w]);
        sMaxW[0] = m;
    }
    __syncthreads();
    float Dmax = sMaxW[0];

    unsigned long long keys[4];
    #pragma unroll
    for (int r = 0; r < 4; r++) {
        float adj = Dv[r] + (1.0f - m2v[r]) * Dmax;
        keys[r] = ((unsigned long long)__float_as_uint(adj) << 32) | (unsigned)(tid + r*256);
        atomicAdd(&hist[(uint32_t)(keys[r] >> 51)], 1u);
    }
    __syncthreads();

    // prefix scan of 256 per-thread partial sums (16 bins each)
    int s = 0;
    #pragma unroll
    for (int u = 0; u < 16; u++) s += (int)hist[tid*16 + u];
    int inc = s;
    #pragma unroll
    for (int off = 1; off < 32; off <<= 1) {
        int v = __shfl_up_sync(0xffffffffu, inc, off);
        if (lane >= off) inc += v;
    }
    if (lane == 31) sWS[warp] = inc;
    __syncthreads();
    if (tid == 0) {
        int acc = 0;
        #pragma unroll
        for (int w = 0; w < 8; w++) { int v = sWS[w]; sWS[w] = acc; acc += v; }
    }
    __syncthreads();
    int excl = inc - s + sWS[warp];
    if (excl < K_ && excl + s >= K_) {
        int c = excl;
        #pragma unroll 1
        for (int u = 0; u < 16; u++) {
            int h = (int)hist[tid*16 + u];
            if (c + h >= K_) { sT = tid*16 + u; break; }
            c += h;
        }
    }
    __syncthreads();
    uint32_t tb = (uint32_t)sT;

    // collect definite (<30) and tie candidates
    #pragma unroll
    for (int r = 0; r < 4; r++) {
        uint32_t bn = (uint32_t)(keys[r] >> 51);
        if (bn < tb) {
            int p = atomicAdd(&sCnt[0], 1);
            defL[p] = keys[r];
        } else if (bn == tb) {
            int p = atomicAdd(&sCnt[1], 1);
            if (p < 320) tieL[p] = keys[r];
        }
    }
    __syncthreads();

    int dc = sCnt[0];                       // == cum before threshold bin, < 30
    int tc = sCnt[1] < 320 ? sCnt[1] : 320;
    if (tid < dc) {
        unsigned long long k = defL[tid];
        int r = 0;
        for (int j2 = 0; j2 < dc; j2++) r += (defL[j2] < k);
        int j = (int)(k & 0xffffffffu);
        g_Eidx[bi*K_ + r]   = j;
        outEidxF[bi*K_ + r] = (float)j;
    }
    if (tid < tc) {
        unsigned long long k = tieL[tid];
        int r = 0;
        for (int j2 = 0; j2 < tc; j2++) r += (tieL[j2] < k);
        int slot = dc + r;
        if (slot < K_) {
            int j = (int)(k & 0xffffffffu);
            g_Eidx[bi*K_ + slot]   = j;
            outEidxF[bi*K_ + slot] = (float)j;
        }
    }
}

// ================= kernel 3: HMMA edge kernel (fp16 single-pass) =================
// (unchanged from R13: 64 edges/block, 3 CTAs/SM, XOR swizzle, fp16 A & W,
//  RBF geometric recurrence, double-buffered, one sync/chunk)

// smem offsets (bytes)
#define SM_RED   0        // 64*8 floats = 2048
#define SM_SD    2048     // 256
#define SM_SI    2304     // 256
#define SM_SN    2560     // 256
#define SM_WPE   2816     // 4224 -> 7040
#define SM_BPE   7040     // 64
#define SM_LNW   7104     // 512
#define SM_LNB   7616     // 512 -> 8128
#define SM_DIST  8128     // 6400 -> 14528
#define SM_TILES 15360    // 2 buffers * 24576 = 49152
#define SM_STAGE SM_TILES // 64*132*4 = 33792 (reuses tiles post-GEMM)
#define SMEM_BYTES (SM_TILES + 2*BUFSZ_)   // 64512

#define SWO(r, c) ((uint32_t)((r)*128 + (((c) ^ ((r) & 7)) << 4)))

__device__ __forceinline__ void gen16(int pr, int sde,
                                      const float* __restrict__ Wpe_s,
                                      const float* __restrict__ bpe_s,
                                      const float* __restrict__ dist_e,
                                      float* v) {
    if (pr < 0) {
        #pragma unroll
        for (int u = 0; u < 16; u++) v[u] = Wpe_s[u*PEC_ + sde] + bpe_s[u];
    } else if (pr < 25) {
        const float s  = 1.06666672f;      // 0.8 * 20/15
        const float s2 = 1.13777781f;      // s^2
        const float cc = 0.10273956f;      // exp(-2*s^2)
        float d = dist_e[pr];
        if (d < 12.5f) {
            float t0 = (d - 2.0f) * 0.8f;
            float e = __expf(-t0*t0);
            float r = __expf(2.0f*s*t0 - s2);
            v[0] = e;
            #pragma unroll
            for (int m = 1; m < 16; m++) { e *= r; r *= cc; v[m] = e; }
        } else {
            float t15 = (d - 22.0f) * 0.8f;
            float e = __expf(-t15*t15);
            float sg = __expf(-2.0f*s*t15 - s2);
            v[15] = e;
            #pragma unroll
            for (int m = 14; m >= 0; m--) { e *= sg; sg *= cc; v[m] = e; }
        }
    } else {
        #pragma unroll
        for (int u = 0; u < 16; u++) v[u] = 0.0f;
    }
}

__global__ __launch_bounds__(256, 3) void edge_kernel(
    const int*   __restrict__ ridx,
    const int*   __restrict__ clab,
    const float* __restrict__ W_pe,
    const float* __restrict__ b_pe,
    const float* __restrict__ ln_w,
    const float* __restrict__ ln_b,
    float*       __restrict__ outE)
{
    extern __shared__ char smem[];
    uint32_t sb = smem_u32(smem);
    int tid = threadIdx.x, lane = tid & 31, wid = tid >> 5;
    int blk = blockIdx.x;

    float* red    = (float*)(smem + SM_RED);
    int*   sd     = (int*)  (smem + SM_SD);
    int*   sI     = (int*)  (smem + SM_SI);
    int*   sN     = (int*)  (smem + SM_SN);
    float* Wpe_s  = (float*)(smem + SM_WPE);
    float* bpe_s  = (float*)(smem + SM_BPE);
    float* lnw_s  = (float*)(smem + SM_LNW);
    float* lnb_s  = (float*)(smem + SM_LNB);
    float* dist_s = (float*)(smem + SM_DIST);

    for (int i = tid; i < NPE_*PEC_; i += 256) Wpe_s[i] = W_pe[i];
    if (tid < NPE_) bpe_s[tid] = b_pe[tid];
    if (tid < EF_)  { lnw_s[tid] = ln_w[tid]; lnb_s[tid] = ln_b[tid]; }

    if (tid < EB_) {
        int eg  = blk*EB_ + tid;
        int b   = eg / (L_*K_);
        int r   = eg % (L_*K_);
        int i   = r / K_;
        int nbr = g_Eidx[eg];
        int gi = b*L_ + i, gn = b*L_ + nbr;
        sI[tid] = gi; sN[tid] = gn;
        int off  = ridx[gi] - ridx[gn];
        int same = (clab[gi] == clab[gn]);
        int c = off + 32; c = c < 0 ? 0 : (c > 64 ? 64 : c);
        sd[tid] = same ? c : 65;
    }
    __syncthreads();

    for (int w = tid; w < EB_*25; w += 256) {
        int e = w / 25, p = w % 25;
        int a = p / 5, bb = p % 5;
        const float* xi = g_X5 + sI[e]*15 + a*3;
        const float* xn = g_X5 + sN[e]*15 + bb*3;
        float dx = xi[0]-xn[0], dy = xi[1]-xn[1], dz = xi[2]-xn[2];
        dist_s[w] = sqrtf(dx*dx + dy*dy + dz*dz + 1e-6f);
    }
    __syncthreads();

    int mw = wid >> 2, nw = wid & 3;
    int arow    = mw*32 + ((lane>>3)&1)*8 + (lane&7);
    uint32_t achunk0 = (uint32_t)(lane>>4);
    uint32_t aRowBase = (uint32_t)(arow*128);
    uint32_t aRS      = (uint32_t)(arow & 7);
    int brow_l  = nw*32 + (lane>>4)*8 + (lane&7);
    uint32_t bchunk0 = (uint32_t)((lane>>3)&1);
    uint32_t bRowBase = (uint32_t)(brow_l*128);
    uint32_t bRS      = (uint32_t)(brow_l & 7);

    int fe = tid >> 2;
    int q  = tid & 3;
    const float* dist_e = dist_s + fe*25;
    int sde = sd[fe];
    uint32_t aFillOff0 = SWO(fe, q*2);
    uint32_t aFillOff1 = SWO(fe, q*2+1);

    float acc[2][4][4];
    #pragma unroll
    for (int mt = 0; mt < 2; mt++)
        #pragma unroll
        for (int nt = 0; nt < 4; nt++)
            #pragma unroll
            for (int i = 0; i < 4; i++) acc[mt][nt][i] = 0.0f;

    {
        uint32_t bt = sb + SM_TILES + ATSZ_;
        #pragma unroll
        for (int it = 0; it < 4; it++) {
            int i = tid + it*256;
            int n = i >> 3, g = i & 7;
            cpasync16(bt + SWO(n, g), g_Wh + n*KPAD_ + g*8);
        }
        CP_COMMIT();
        float v[16];
        gen16(q - 1, sde, Wpe_s, bpe_s, dist_e, v);
        uint32_t hw[8];
        #pragma unroll
        for (int u = 0; u < 8; u++) hw[u] = pkh2(v[2*u], v[2*u+1]);
        uint32_t ah = sb + SM_TILES;
        sts128(ah + aFillOff0, hw[0], hw[1], hw[2], hw[3]);
        sts128(ah + aFillOff1, hw[4], hw[5], hw[6], hw[7]);
        CP_WAIT0();
    }
    __syncthreads();

    #pragma unroll 1
    for (int c = 0; c < NCH_; c++) {
        uint32_t cur = sb + SM_TILES + (uint32_t)(c & 1) * BUFSZ_;
        uint32_t nxt = sb + SM_TILES + (uint32_t)((c+1) & 1) * BUFSZ_;

        if (c + 1 < NCH_) {
            uint32_t bt = nxt + ATSZ_;
            #pragma unroll
            for (int it = 0; it < 4; it++) {
                int i = tid + it*256;
                int n = i >> 3, g = i & 7;
                cpasync16(bt + SWO(n, g), g_Wh + n*KPAD_ + (c+1)*KC_ + g*8);
            }
            CP_COMMIT();
        }

        uint32_t At = cur, Bt = cur + ATSZ_;
        #pragma unroll
        for (int ks = 0; ks < 4; ks++) {
            uint32_t aOff = aRowBase + ((((uint32_t)(2*ks) + achunk0) ^ aRS) << 4);
            uint32_t bOff = bRowBase + ((((uint32_t)(2*ks) + bchunk0) ^ bRS) << 4);
            uint32_t ah[8], bf[8];
            ldsm4(ah,     At + aOff);
            ldsm4(ah + 4, At + aOff + 2048);
            ldsm4(bf,     Bt + bOff);
            ldsm4(bf + 4, Bt + bOff + 2048);
            #pragma unroll
            for (int mt = 0; mt < 2; mt++)
                #pragma unroll
                for (int nt = 0; nt < 4; nt++)
                    mma16816(acc[mt][nt], ah + 4*mt, bf + 2*nt);
        }

        if (c + 1 < NCH_) {
            float v[16];
            gen16(4*(c+1) + q - 1, sde, Wpe_s, bpe_s, dist_e, v);
            uint32_t hw[8];
            #pragma unroll
            for (int u = 0; u < 8; u++) hw[u] = pkh2(v[2*u], v[2*u+1]);
            sts128(nxt + aFillOff0, hw[0], hw[1], hw[2], hw[3]);
            sts128(nxt + aFillOff1, hw[4], hw[5], hw[6], hw[7]);
        }
        CP_WAIT0();
        __syncthreads();
    }

    // epilogue: LayerNorm + staged store
    int qrow = lane >> 2;
    #pragma unroll
    for (int mt = 0; mt < 2; mt++) {
        #pragma unroll
        for (int h = 0; h < 2; h++) {
            float s = 0.f, sq = 0.f;
            #pragma unroll
            for (int nt = 0; nt < 4; nt++) {
                float v0 = acc[mt][nt][2*h], v1 = acc[mt][nt][2*h+1];
                s += v0 + v1; sq += v0*v0 + v1*v1;
            }
            s  += __shfl_xor_sync(0xffffffffu, s, 1);
            sq += __shfl_xor_sync(0xffffffffu, sq, 1);
            s  += __shfl_xor_sync(0xffffffffu, s, 2);
            sq += __shfl_xor_sync(0xffffffffu, sq, 2);
            if ((lane & 3) == 0) {
                int row = mw*32 + mt*16 + h*8 + qrow;
                red[row*8 + nw*2 + 0] = s;
                red[row*8 + nw*2 + 1] = sq;
            }
        }
    }
    __syncthreads();

    float* stage = (float*)(smem + SM_STAGE);
    float2 lw2[4], lb2[4];
    int cq = 2*(lane & 3);
    #pragma unroll
    for (int nt = 0; nt < 4; nt++) {
        lw2[nt] = *(float2*)(lnw_s + nw*32 + nt*8 + cq);
        lb2[nt] = *(float2*)(lnb_s + nw*32 + nt*8 + cq);
    }
    #pragma unroll
    for (int mt = 0; mt < 2; mt++) {
        #pragma unroll
        for (int h = 0; h < 2; h++) {
            int row = mw*32 + mt*16 + h*8 + qrow;
            float sum = red[row*8 + 0] + red[row*8 + 2] + red[row*8 + 4] + red[row*8 + 6];
            float sq  = red[row*8 + 1] + red[row*8 + 3] + red[row*8 + 5] + red[row*8 + 7];
            float mean = sum * (1.0f/128.0f);
            float var  = sq * (1.0f/128.0f) - mean*mean;
            float rstd = rsqrtf(var + 1e-5f);
            float* srow = stage + row*132 + nw*32 + cq;
            #pragma unroll
            for (int nt = 0; nt < 4; nt++) {
                float2 o;
                o.x = (acc[mt][nt][2*h]   - mean)*rstd*lw2[nt].x + lb2[nt].x;
                o.y = (acc[mt][nt][2*h+1] - mean)*rstd*lw2[nt].y + lb2[nt].y;
                *(float2*)(srow + nt*8) = o;
            }
        }
    }
    __syncthreads();

    {
        float4* dst = (float4*)(outE + (size_t)blk * EB_ * EF_);
        #pragma unroll 1
        for (int i = tid; i < EB_*EF_/4; i += 256) {
            int row = i >> 5, c4 = i & 31;
            dst[i] = *(float4*)(stage + row*132 + c4*4);
        }
    }
}

// ---------------------------------------------------------------------------
extern "C" void kernel_launch(void* const* d_in, const int* in_sizes, int n_in,
                              void* d_out, int out_size) {
    (void)in_sizes; (void)n_in; (void)out_size;
    const float* X      = (const float*)d_in[0];
    const float* mask   = (const float*)d_in[1];
    const int*   ridx   = (const int*)  d_in[2];
    const int*   clab   = (const int*)  d_in[3];
    const float* W_pe   = (const float*)d_in[4];
    const float* b_pe   = (const float*)d_in[5];
    const float* W_edge = (const float*)d_in[6];
    const float* ln_w   = (const float*)d_in[7];
    const float* ln_b   = (const float*)d_in[8];

    float* out      = (float*)d_out;
    float* outE     = out;                                   // B*L*K*128
    float* outEidxF = out + (size_t)NEDGE * EF_;             // B*L*K (as float)
    float* outX     = outEidxF + (size_t)NEDGE;              // B*L*4*3

    cudaFuncSetAttribute(edge_kernel, cudaFuncAttributeMaxDynamicSharedMemorySize, SMEM_BYTES);

    prep_kernel<<<(EF_*KPAD_ + 255)/256, 256>>>(X, W_edge, outX);
    topk_kernel<<<B_*L_, 256>>>(X, mask, outEidxF);
    edge_kernel<<<NEDGE/EB_, 256, SMEM_BYTES>>>(ridx, clab, W_pe, b_pe, ln_w, ln_b, outE);
}

// round 15
// speedup vs baseline: 5.9740x; 1.2736x over previous
#include <cuda_runtime.h>
#include <cuda_fp16.h>
#include <cstdint>

// ---------------- problem constants ----------------
#define B_    8
#define L_    1024
#define K_    30
#define EF_   128          // EDGE_FEATURES (= N)
#define EIN_  416          // NUM_PE + NUM_RBF*25 (= K)
#define KPAD_ 448          // K padded to 7*64
#define NPE_  16
#define PEC_  66           // 2*MAX_REL+2
#define NEDGE (B_*L_*K_)   // 245760

// ---------------- edge-kernel tiling ----------------
#define EB_   64           // edges per block (= M)
#define KC_   64           // k per chunk (= 128 bytes/row fp16)
#define NCH_  7            // KPAD_/KC_
#define ATSZ_ 8192         // A tile: 64 rows * 128B
#define BTSZ_ 16384        // B tile: 128 rows * 128B
#define BUFSZ_ (ATSZ_ + BTSZ_)       // 24576 per buffer (A, B)

// ---------------- scratch (static device globals) ----------------
__device__ float  g_X5[B_*L_*15];
__device__ float4 g_Ca[B_*L_];       // compacted {Ca.xyz, mask} for topk
__device__ int    g_Eidx[NEDGE];
__device__ __half g_Wh[EF_*KPAD_];   // W_edge fp16, [n][k] k-major, zero-padded

// ================= helpers =================
__device__ __forceinline__ uint32_t smem_u32(const void* p) {
    uint32_t a;
    asm("{ .reg .u64 t; cvta.to.shared.u64 t, %1; cvt.u32.u64 %0, t; }" : "=r"(a) : "l"(p));
    return a;
}
__device__ __forceinline__ void sts128(uint32_t addr, uint32_t a, uint32_t b, uint32_t c, uint32_t d) {
    asm volatile("st.shared.v4.b32 [%0], {%1,%2,%3,%4};" :: "r"(addr), "r"(a), "r"(b), "r"(c), "r"(d) : "memory");
}
__device__ __forceinline__ void ldsm4(uint32_t* r, uint32_t addr) {
    asm volatile("ldmatrix.sync.aligned.m8n8.x4.shared.b16 {%0,%1,%2,%3}, [%4];"
        : "=r"(r[0]), "=r"(r[1]), "=r"(r[2]), "=r"(r[3]) : "r"(addr));
}
__device__ __forceinline__ void mma16816(float (&d)[4], const uint32_t* a, const uint32_t* b) {
    asm volatile("mma.sync.aligned.m16n8k16.row.col.f32.f16.f16.f32 "
        "{%0,%1,%2,%3}, {%4,%5,%6,%7}, {%8,%9}, {%0,%1,%2,%3};"
        : "+f"(d[0]), "+f"(d[1]), "+f"(d[2]), "+f"(d[3])
        : "r"(a[0]), "r"(a[1]), "r"(a[2]), "r"(a[3]), "r"(b[0]), "r"(b[1]));
}
__device__ __forceinline__ uint32_t pkh2(float a, float b) {
    __half2 h = __floats2half2_rn(a, b);    // low = a
    return *(uint32_t*)&h;
}
__device__ __forceinline__ void cpasync16(uint32_t dst, const void* src) {
    asm volatile("cp.async.cg.shared.global [%0], [%1], 16;" :: "r"(dst), "l"(src) : "memory");
}
#define CP_COMMIT() asm volatile("cp.async.commit_group;" ::: "memory")
#define CP_WAIT0()  asm volatile("cp.async.wait_group 0;" ::: "memory")

// ================= kernel 1: fused X5 + Ca-compact + X passthrough + W->fp16 =================
__global__ void prep_kernel(const float* __restrict__ X, const float* __restrict__ W,
                            const float* __restrict__ mask, float* __restrict__ outX) {
    int t = blockIdx.x * blockDim.x + threadIdx.x;
    if (t < B_*L_) {
        const float* x = X + (size_t)t * 12;
        float x0x=x[0], x0y=x[1],  x0z=x[2];
        float x1x=x[3], x1y=x[4],  x1z=x[5];
        float x2x=x[6], x2y=x[7],  x2z=x[8];
        float bx=x1x-x0x, by=x1y-x0y, bz=x1z-x0z;
        float cx=x2x-x1x, cy=x2y-x1y, cz=x2z-x1z;
        float ax=by*cz-bz*cy, ay=bz*cx-bx*cz, az=bx*cy-by*cx;
        float* o = g_X5 + t*15;
        #pragma unroll
        for (int i = 0; i < 12; i++) { o[i] = x[i]; outX[(size_t)t*12 + i] = x[i]; }
        o[12] = -0.58273431f*ax + 0.56802827f*bx - 0.54067466f*cx + x1x;
        o[13] = -0.58273431f*ay + 0.56802827f*by - 0.54067466f*cy + x1y;
        o[14] = -0.58273431f*az + 0.56802827f*bz - 0.54067466f*cz + x1z;
        g_Ca[t] = make_float4(x1x, x1y, x1z, mask[t]);
    }
    if (t < EF_*KPAD_) {
        int n = t / KPAD_, k = t % KPAD_;
        float w = (k < EIN_) ? W[n*EIN_ + k] : 0.0f;
        g_Wh[t] = __float2half_rn(w);
    }
}

// ================= kernel 2: radix-select top-30 (compacted Ca loads) =================
#define NBIN_ 4096
__global__ __launch_bounds__(256) void topk_kernel(float* __restrict__ outEidxF) {
    __shared__ __align__(16) unsigned int hist[NBIN_];   // 16 KB
    __shared__ float sMaxW[8];
    __shared__ int   sWS[8];
    __shared__ int   sT, sCnt[2];
    __shared__ unsigned long long defL[32];
    __shared__ unsigned long long tieL[320];

    int bi = blockIdx.x;
    int b  = bi >> 10;
    int tid = threadIdx.x, lane = tid & 31, warp = tid >> 5;

    const float4* cb = g_Ca + (size_t)b * L_;
    int il = bi & (L_-1);
    float4 ci = cb[il];
    float mi = ci.w;

    float Dv[4], m2v[4];
    float lmax = -1e30f;
    #pragma unroll
    for (int r = 0; r < 4; r++) {
        int j = tid + r*256;
        float4 cj = cb[j];
        float dx = ci.x - cj.x, dy = ci.y - cj.y, dz = ci.z - cj.z;
        float m2 = mi * cj.w;
        float D  = m2 * sqrtf(dx*dx + dy*dy + dz*dz + 1e-6f);
        Dv[r] = D; m2v[r] = m2;
        lmax = fmaxf(lmax, D);
    }
    #pragma unroll
    for (int off = 16; off; off >>= 1)
        lmax = fmaxf(lmax, __shfl_xor_sync(0xffffffffu, lmax, off));
    if (lane == 0) sMaxW[warp] = lmax;

    // zero histogram (uint4) + counters while max lands
    {
        uint4 z = make_uint4(0,0,0,0);
        uint4* h4 = (uint4*)hist;
        #pragma unroll
        for (int u = 0; u < NBIN_/4/256; u++) h4[tid + u*256] = z;
    }
    if (tid == 0) { sCnt[0] = 0; sCnt[1] = 0; }
    __syncthreads();
    if (tid == 0) {
        float m = sMaxW[0];
        #pragma unroll
        for (int w = 1; w < 8; w++) m = fmaxf(m, sMaxW[w]);
        sMaxW[0] = m;
    }
    __syncthreads();
    float Dmax = sMaxW[0];

    unsigned long long keys[4];
    #pragma unroll
    for (int r = 0; r < 4; r++) {
        float adj = Dv[r] + (1.0f - m2v[r]) * Dmax;
        keys[r] = ((unsigned long long)__float_as_uint(adj) << 32) | (unsigned)(tid + r*256);
        atomicAdd(&hist[(uint32_t)(keys[r] >> 51)], 1u);
    }
    __syncthreads();

    // prefix scan of 256 per-thread partial sums (16 bins each)
    int s = 0;
    #pragma unroll
    for (int u = 0; u < 16; u++) s += (int)hist[tid*16 + u];
    int inc = s;
    #pragma unroll
    for (int off = 1; off < 32; off <<= 1) {
        int v = __shfl_up_sync(0xffffffffu, inc, off);
        if (lane >= off) inc += v;
    }
    if (lane == 31) sWS[warp] = inc;
    __syncthreads();
    if (tid == 0) {
        int acc = 0;
        #pragma unroll
        for (int w = 0; w < 8; w++) { int v = sWS[w]; sWS[w] = acc; acc += v; }
    }
    __syncthreads();
    int excl = inc - s + sWS[warp];
    if (excl < K_ && excl + s >= K_) {
        int c = excl;
        #pragma unroll 1
        for (int u = 0; u < 16; u++) {
            int h = (int)hist[tid*16 + u];
            if (c + h >= K_) { sT = tid*16 + u; break; }
            c += h;
        }
    }
    __syncthreads();
    uint32_t tb = (uint32_t)sT;

    // collect definite (<30) and tie candidates
    #pragma unroll
    for (int r = 0; r < 4; r++) {
        uint32_t bn = (uint32_t)(keys[r] >> 51);
        if (bn < tb) {
            int p = atomicAdd(&sCnt[0], 1);
            defL[p] = keys[r];
        } else if (bn == tb) {
            int p = atomicAdd(&sCnt[1], 1);
            if (p < 320) tieL[p] = keys[r];
        }
    }
    __syncthreads();

    int dc = sCnt[0];
    int tc = sCnt[1] < 320 ? sCnt[1] : 320;
    if (tid < dc) {
        unsigned long long k = defL[tid];
        int r = 0;
        for (int j2 = 0; j2 < dc; j2++) r += (defL[j2] < k);
        int j = (int)(k & 0xffffffffu);
        g_Eidx[bi*K_ + r]   = j;
        outEidxF[bi*K_ + r] = (float)j;
    }
    if (tid < tc) {
        unsigned long long k = tieL[tid];
        int r = 0;
        for (int j2 = 0; j2 < tc; j2++) r += (tieL[j2] < k);
        int slot = dc + r;
        if (slot < K_) {
            int j = (int)(k & 0xffffffffu);
            g_Eidx[bi*K_ + slot]   = j;
            outEidxF[bi*K_ + slot] = (float)j;
        }
    }
}

// ================= kernel 3: HMMA edge kernel (fp16 single-pass) =================
// As R13/R14, plus: LN epilogue stores directly to global (float2 per (row,nt);
// each lane-quad covers a contiguous 32B sector) — no smem stage round-trip.

// smem offsets (bytes)
#define SM_RED   0        // 64*8 floats = 2048
#define SM_SD    2048     // 256
#define SM_SI    2304     // 256
#define SM_SN    2560     // 256
#define SM_WPE   2816     // 4224 -> 7040
#define SM_BPE   7040     // 64
#define SM_LNW   7104     // 512
#define SM_LNB   7616     // 512 -> 8128
#define SM_DIST  8128     // 6400 -> 14528
#define SM_TILES 15360    // 2 buffers * 24576 = 49152
#define SMEM_BYTES (SM_TILES + 2*BUFSZ_)   // 64512

#define SWO(r, c) ((uint32_t)((r)*128 + (((c) ^ ((r) & 7)) << 4)))

__device__ __forceinline__ void gen16(int pr, int sde,
                                      const float* __restrict__ Wpe_s,
                                      const float* __restrict__ bpe_s,
                                      const float* __restrict__ dist_e,
                                      float* v) {
    if (pr < 0) {
        #pragma unroll
        for (int u = 0; u < 16; u++) v[u] = Wpe_s[u*PEC_ + sde] + bpe_s[u];
    } else if (pr < 25) {
        const float s  = 1.06666672f;      // 0.8 * 20/15
        const float s2 = 1.13777781f;      // s^2
        const float cc = 0.10273956f;      // exp(-2*s^2)
        float d = dist_e[pr];
        if (d < 12.5f) {
            float t0 = (d - 2.0f) * 0.8f;
            float e = __expf(-t0*t0);
            float r = __expf(2.0f*s*t0 - s2);
            v[0] = e;
            #pragma unroll
            for (int m = 1; m < 16; m++) { e *= r; r *= cc; v[m] = e; }
        } else {
            float t15 = (d - 22.0f) * 0.8f;
            float e = __expf(-t15*t15);
            float sg = __expf(-2.0f*s*t15 - s2);
            v[15] = e;
            #pragma unroll
            for (int m = 14; m >= 0; m--) { e *= sg; sg *= cc; v[m] = e; }
        }
    } else {
        #pragma unroll
        for (int u = 0; u < 16; u++) v[u] = 0.0f;
    }
}

__global__ __launch_bounds__(256, 3) void edge_kernel(
    const int*   __restrict__ ridx,
    const int*   __restrict__ clab,
    const float* __restrict__ W_pe,
    const float* __restrict__ b_pe,
    const float* __restrict__ ln_w,
    const float* __restrict__ ln_b,
    float*       __restrict__ outE)
{
    extern __shared__ char smem[];
    uint32_t sb = smem_u32(smem);
    int tid = threadIdx.x, lane = tid & 31, wid = tid >> 5;
    int blk = blockIdx.x;

    float* red    = (float*)(smem + SM_RED);
    int*   sd     = (int*)  (smem + SM_SD);
    int*   sI     = (int*)  (smem + SM_SI);
    int*   sN     = (int*)  (smem + SM_SN);
    float* Wpe_s  = (float*)(smem + SM_WPE);
    float* bpe_s  = (float*)(smem + SM_BPE);
    float* lnw_s  = (float*)(smem + SM_LNW);
    float* lnb_s  = (float*)(smem + SM_LNB);
    float* dist_s = (float*)(smem + SM_DIST);

    for (int i = tid; i < NPE_*PEC_; i += 256) Wpe_s[i] = W_pe[i];
    if (tid < NPE_) bpe_s[tid] = b_pe[tid];
    if (tid < EF_)  { lnw_s[tid] = ln_w[tid]; lnb_s[tid] = ln_b[tid]; }

    if (tid < EB_) {
        int eg  = blk*EB_ + tid;
        int b   = eg / (L_*K_);
        int r   = eg % (L_*K_);
        int i   = r / K_;
        int nbr = g_Eidx[eg];
        int gi = b*L_ + i, gn = b*L_ + nbr;
        sI[tid] = gi; sN[tid] = gn;
        int off  = ridx[gi] - ridx[gn];
        int same = (clab[gi] == clab[gn]);
        int c = off + 32; c = c < 0 ? 0 : (c > 64 ? 64 : c);
        sd[tid] = same ? c : 65;
    }
    __syncthreads();

    for (int w = tid; w < EB_*25; w += 256) {
        int e = w / 25, p = w % 25;
        int a = p / 5, bb = p % 5;
        const float* xi = g_X5 + sI[e]*15 + a*3;
        const float* xn = g_X5 + sN[e]*15 + bb*3;
        float dx = xi[0]-xn[0], dy = xi[1]-xn[1], dz = xi[2]-xn[2];
        dist_s[w] = sqrtf(dx*dx + dy*dy + dz*dz + 1e-6f);
    }
    __syncthreads();

    int mw = wid >> 2, nw = wid & 3;
    int arow    = mw*32 + ((lane>>3)&1)*8 + (lane&7);
    uint32_t achunk0 = (uint32_t)(lane>>4);
    uint32_t aRowBase = (uint32_t)(arow*128);
    uint32_t aRS      = (uint32_t)(arow & 7);
    int brow_l  = nw*32 + (lane>>4)*8 + (lane&7);
    uint32_t bchunk0 = (uint32_t)((lane>>3)&1);
    uint32_t bRowBase = (uint32_t)(brow_l*128);
    uint32_t bRS      = (uint32_t)(brow_l & 7);

    int fe = tid >> 2;
    int q  = tid & 3;
    const float* dist_e = dist_s + fe*25;
    int sde = sd[fe];
    uint32_t aFillOff0 = SWO(fe, q*2);
    uint32_t aFillOff1 = SWO(fe, q*2+1);

    float acc[2][4][4];
    #pragma unroll
    for (int mt = 0; mt < 2; mt++)
        #pragma unroll
        for (int nt = 0; nt < 4; nt++)
            #pragma unroll
            for (int i = 0; i < 4; i++) acc[mt][nt][i] = 0.0f;

    {
        uint32_t bt = sb + SM_TILES + ATSZ_;
        #pragma unroll
        for (int it = 0; it < 4; it++) {
            int i = tid + it*256;
            int n = i >> 3, g = i & 7;
            cpasync16(bt + SWO(n, g), g_Wh + n*KPAD_ + g*8);
        }
        CP_COMMIT();
        float v[16];
        gen16(q - 1, sde, Wpe_s, bpe_s, dist_e, v);
        uint32_t hw[8];
        #pragma unroll
        for (int u = 0; u < 8; u++) hw[u] = pkh2(v[2*u], v[2*u+1]);
        uint32_t ah = sb + SM_TILES;
        sts128(ah + aFillOff0, hw[0], hw[1], hw[2], hw[3]);
        sts128(ah + aFillOff1, hw[4], hw[5], hw[6], hw[7]);
        CP_WAIT0();
    }
    __syncthreads();

    #pragma unroll 1
    for (int c = 0; c < NCH_; c++) {
        uint32_t cur = sb + SM_TILES + (uint32_t)(c & 1) * BUFSZ_;
        uint32_t nxt = sb + SM_TILES + (uint32_t)((c+1) & 1) * BUFSZ_;

        if (c + 1 < NCH_) {
            uint32_t bt = nxt + ATSZ_;
            #pragma unroll
            for (int it = 0; it < 4; it++) {
                int i = tid + it*256;
                int n = i >> 3, g = i & 7;
                cpasync16(bt + SWO(n, g), g_Wh + n*KPAD_ + (c+1)*KC_ + g*8);
            }
            CP_COMMIT();
        }

        uint32_t At = cur, Bt = cur + ATSZ_;
        #pragma unroll
        for (int ks = 0; ks < 4; ks++) {
            uint32_t aOff = aRowBase + ((((uint32_t)(2*ks) + achunk0) ^ aRS) << 4);
            uint32_t bOff = bRowBase + ((((uint32_t)(2*ks) + bchunk0) ^ bRS) << 4);
            uint32_t ah[8], bf[8];
            ldsm4(ah,     At + aOff);
            ldsm4(ah + 4, At + aOff + 2048);
            ldsm4(bf,     Bt + bOff);
            ldsm4(bf + 4, Bt + bOff + 2048);
            #pragma unroll
            for (int mt = 0; mt < 2; mt++)
                #pragma unroll
                for (int nt = 0; nt < 4; nt++)
                    mma16816(acc[mt][nt], ah + 4*mt, bf + 2*nt);
        }

        if (c + 1 < NCH_) {
            float v[16];
            gen16(4*(c+1) + q - 1, sde, Wpe_s, bpe_s, dist_e, v);
            uint32_t hw[8];
            #pragma unroll
            for (int u = 0; u < 8; u++) hw[u] = pkh2(v[2*u], v[2*u+1]);
            sts128(nxt + aFillOff0, hw[0], hw[1], hw[2], hw[3]);
            sts128(nxt + aFillOff1, hw[4], hw[5], hw[6], hw[7]);
        }
        CP_WAIT0();
        __syncthreads();
    }

    // ---------------- epilogue: LayerNorm + direct global store ----------------
    int qrow = lane >> 2;
    #pragma unroll
    for (int mt = 0; mt < 2; mt++) {
        #pragma unroll
        for (int h = 0; h < 2; h++) {
            float s = 0.f, sq = 0.f;
            #pragma unroll
            for (int nt = 0; nt < 4; nt++) {
                float v0 = acc[mt][nt][2*h], v1 = acc[mt][nt][2*h+1];
                s += v0 + v1; sq += v0*v0 + v1*v1;
            }
            s  += __shfl_xor_sync(0xffffffffu, s, 1);
            sq += __shfl_xor_sync(0xffffffffu, sq, 1);
            s  += __shfl_xor_sync(0xffffffffu, s, 2);
            sq += __shfl_xor_sync(0xffffffffu, sq, 2);
            if ((lane & 3) == 0) {
                int row = mw*32 + mt*16 + h*8 + qrow;
                red[row*8 + nw*2 + 0] = s;
                red[row*8 + nw*2 + 1] = sq;
            }
        }
    }
    __syncthreads();

    float2 lw2[4], lb2[4];
    int cq = 2*(lane & 3);
    #pragma unroll
    for (int nt = 0; nt < 4; nt++) {
        lw2[nt] = *(float2*)(lnw_s + nw*32 + nt*8 + cq);
        lb2[nt] = *(float2*)(lnb_s + nw*32 + nt*8 + cq);
    }
    #pragma unroll
    for (int mt = 0; mt < 2; mt++) {
        #pragma unroll
        for (int h = 0; h < 2; h++) {
            int row = mw*32 + mt*16 + h*8 + qrow;
            float sum = red[row*8 + 0] + red[row*8 + 2] + red[row*8 + 4] + red[row*8 + 6];
            float sq  = red[row*8 + 1] + red[row*8 + 3] + red[row*8 + 5] + red[row*8 + 7];
            float mean = sum * (1.0f/128.0f);
            float var  = sq * (1.0f/128.0f) - mean*mean;
            float rstd = rsqrtf(var + 1e-5f);
            float* orow = outE + (size_t)(blk*EB_ + row) * EF_ + nw*32 + cq;
            #pragma unroll
            for (int nt = 0; nt < 4; nt++) {
                float2 o;
                o.x = (acc[mt][nt][2*h]   - mean)*rstd*lw2[nt].x + lb2[nt].x;
                o.y = (acc[mt][nt][2*h+1] - mean)*rstd*lw2[nt].y + lb2[nt].y;
                *(float2*)(orow + nt*8) = o;
            }
        }
    }
}

// ---------------------------------------------------------------------------
extern "C" void kernel_launch(void* const* d_in, const int* in_sizes, int n_in,
                              void* d_out, int out_size) {
    (void)in_sizes; (void)n_in; (void)out_size;
    const float* X      = (const float*)d_in[0];
    const float* mask   = (const float*)d_in[1];
    const int*   ridx   = (const int*)  d_in[2];
    const int*   clab   = (const int*)  d_in[3];
    const float* W_pe   = (const float*)d_in[4];
    const float* b_pe   = (const float*)d_in[5];
    const float* W_edge = (const float*)d_in[6];
    const float* ln_w   = (const float*)d_in[7];
    const float* ln_b   = (const float*)d_in[8];

    float* out      = (float*)d_out;
    float* outE     = out;                                   // B*L*K*128
    float* outEidxF = out + (size_t)NEDGE * EF_;             // B*L*K (as float)
    float* outX     = outEidxF + (size_t)NEDGE;              // B*L*4*3

    cudaFuncSetAttribute(edge_kernel, cudaFuncAttributeMaxDynamicSharedMemorySize, SMEM_BYTES);

    prep_kernel<<<(EF_*KPAD_ + 255)/256, 256>>>(X, W_edge, mask, outX);
    topk_kernel<<<B_*L_, 256>>>(outEidxF);
    edge_kernel<<<NEDGE/EB_, 256, SMEM_BYTES>>>(ridx, clab, W_pe, b_pe, ln_w, ln_b, outE);
}